// round 6
// baseline (speedup 1.0000x reference)
#include <cuda_runtime.h>
#include <math.h>

#define Bv 256
#define Sv 512
#define Avv 64
#define Hv 1024
#define Zv 256
#define H3 3072
#define KS1 4
#define KS2 8

// ---------------- device scratch (static: no allocations) ----------------
__device__ float g_hbuf[2][Bv * Hv];
__device__ float g_PX[Avv * Hv];
__device__ float g_ENCX[Avv * Hv];
__device__ float g_GIX[Avv * H3];
__device__ float g_h1encp[KS1][Bv * Hv];
__device__ float g_h1prip[KS1][Bv * Hv];
__device__ float g_ghp[KS1][Bv * H3];
__device__ float g_gip[KS1][Bv * H3];
__device__ float g_pzp[KS1][Bv * Hv];
__device__ float g_hdencp[KS2][Bv * Zv];
__device__ float g_hdprip[KS2][Bv * Zv];
__device__ float g_zbuf[Bv * Zv];
__device__ float g_pz[Bv * Hv];
__device__ float g_fh1[Bv * Hv];
__device__ float g_fpri[Bv * Zv];
__device__ float g_decb[Bv * Hv];
__device__ double g_kldp[1024];
__device__ unsigned g_arrive, g_release, g_work;

// ---------------- helpers ----------------
__device__ __forceinline__ float softplusf(float x) {
    return x > 0.f ? x + log1pf(expf(-x)) : log1pf(expf(x));
}
__device__ __forceinline__ float sigmoidf(float x) {
    return 1.f / (1.f + expf(-x));
}

__device__ __forceinline__ void grid_sync() {
    __syncthreads();
    if (threadIdx.x == 0) {
        __threadfence();
        volatile unsigned* rel = &g_release;
        unsigned gen = *rel;
        if (atomicAdd(&g_arrive, 1u) == gridDim.x - 1u) {
            g_arrive = 0u;
            g_work = 0u;
            __threadfence();
            atomicAdd(&g_release, 1u);
        } else {
            while (*rel == gen) __nanosleep(32);
        }
    }
    __syncthreads();
    __threadfence();
}

__device__ __forceinline__ int next_job(int* sJob) {
    __syncthreads();
    if (threadIdx.x == 0) *sJob = (int)atomicAdd(&g_work, 1u);
    __syncthreads();
    return *sJob;
}

// ======================================================================
// NEW engine: 128x64 tile, 256 threads, 8x4 thread tile, BK=8.
// As[8][132] transposed (As[k][m]); Ws[8][68] transposed (Ws[k][n]).
// acc[i][j]: row ty*8+i, col tx*4+j  (tx=tid&15, ty=tid>>4)
// ======================================================================
__device__ __forceinline__ void mmstep(
    float (&acc)[8][4], const float (*As)[132], const float (*Ws)[68],
    int tx, int ty)
{
#pragma unroll
    for (int k = 0; k < 8; k++) {
        float4 a0 = *(const float4*)&As[k][ty * 8];
        float4 a1 = *(const float4*)&As[k][ty * 8 + 4];
        float4 b  = *(const float4*)&Ws[k][tx * 4];
        acc[0][0] += a0.x * b.x; acc[0][1] += a0.x * b.y; acc[0][2] += a0.x * b.z; acc[0][3] += a0.x * b.w;
        acc[1][0] += a0.y * b.x; acc[1][1] += a0.y * b.y; acc[1][2] += a0.y * b.z; acc[1][3] += a0.y * b.w;
        acc[2][0] += a0.z * b.x; acc[2][1] += a0.z * b.y; acc[2][2] += a0.z * b.z; acc[2][3] += a0.z * b.w;
        acc[3][0] += a0.w * b.x; acc[3][1] += a0.w * b.y; acc[3][2] += a0.w * b.z; acc[3][3] += a0.w * b.w;
        acc[4][0] += a1.x * b.x; acc[4][1] += a1.x * b.y; acc[4][2] += a1.x * b.z; acc[4][3] += a1.x * b.w;
        acc[5][0] += a1.y * b.x; acc[5][1] += a1.y * b.y; acc[5][2] += a1.y * b.z; acc[5][3] += a1.y * b.w;
        acc[6][0] += a1.z * b.x; acc[6][1] += a1.z * b.y; acc[6][2] += a1.z * b.z; acc[6][3] += a1.z * b.w;
        acc[7][0] += a1.w * b.x; acc[7][1] += a1.w * b.y; acc[7][2] += a1.w * b.z; acc[7][3] += a1.w * b.w;
    }
}

// plain: A[128,K] row-major (lda), W[64,K] row-major (ldw)
__device__ __forceinline__ void mm128(
    const float* __restrict__ A, int lda,
    const float* __restrict__ W, int ldw,
    int K, float (&acc)[8][4],
    float (*As)[132], float (*Ws)[68])
{
    const int tid = threadIdx.x;
    const int ra = tid >> 1, ca = (tid & 1) * 4;   // A staging: row, col-group
    const int rw = tid >> 2, cw = (tid & 3) * 2;   // W staging
    const int tx = tid & 15, ty = tid >> 4;
    const float* pa = A + (size_t)ra * lda + ca;
    const float* pw = W + (size_t)rw * ldw + cw;
    float4 av = *(const float4*)pa;
    float2 wv = *(const float2*)pw;
    for (int k0 = 0; k0 < K; k0 += 8) {
        __syncthreads();
        As[ca + 0][ra] = av.x; As[ca + 1][ra] = av.y;
        As[ca + 2][ra] = av.z; As[ca + 3][ra] = av.w;
        Ws[cw + 0][rw] = wv.x; Ws[cw + 1][rw] = wv.y;
        __syncthreads();
        if (k0 + 8 < K) {
            av = *(const float4*)(pa + k0 + 8);
            wv = *(const float2*)(pw + k0 + 8);
        }
        mmstep(acc, As, Ws, tx, ty);
    }
}

// head: A row r, col c built = relu(sum_{q<4} P[q][r,c] + b1[c] (+ tab[x[r]][c]))
// P base pre-offset (m0*Hv + kofs), row stride Hv, partial stride pq=Bv*Hv.
// b1 pre-offset (+kofs); tab pre-offset (+kofs) or null; xc = x + m0*Sv + t.
__device__ __forceinline__ void mm128_head(
    const float* __restrict__ P,
    const float* __restrict__ b1,
    const float* __restrict__ tab, const int* __restrict__ xc,
    const float* __restrict__ W, int ldw,
    int K, float (&acc)[8][4],
    float (*As)[132], float (*Ws)[68])
{
    const int tid = threadIdx.x;
    const int ra = tid >> 1, ca = (tid & 1) * 4;
    const int rw = tid >> 2, cw = (tid & 3) * 2;
    const int tx = tid & 15, ty = tid >> 4;
    const size_t pq = (size_t)Bv * Hv;
    const float* p0 = P + (size_t)ra * Hv + ca;
    const float* pw = W + (size_t)rw * ldw + cw;
    const float* pt = tab ? (tab + (size_t)xc[ra * Sv] * Hv + ca) : nullptr;
    const float* pb = b1 + ca;

    float4 av, bb;
    float2 wv;
    {
        float4 a0 = *(const float4*)(p0);
        float4 a1 = *(const float4*)(p0 + pq);
        float4 a2 = *(const float4*)(p0 + 2 * pq);
        float4 a3 = *(const float4*)(p0 + 3 * pq);
        bb = *(const float4*)(pb);
        av.x = a0.x + a1.x + a2.x + a3.x + bb.x;
        av.y = a0.y + a1.y + a2.y + a3.y + bb.y;
        av.z = a0.z + a1.z + a2.z + a3.z + bb.z;
        av.w = a0.w + a1.w + a2.w + a3.w + bb.w;
        if (pt) {
            float4 tv = *(const float4*)(pt);
            av.x += tv.x; av.y += tv.y; av.z += tv.z; av.w += tv.w;
        }
        av.x = fmaxf(av.x, 0.f); av.y = fmaxf(av.y, 0.f);
        av.z = fmaxf(av.z, 0.f); av.w = fmaxf(av.w, 0.f);
        wv = *(const float2*)pw;
    }
    for (int k0 = 0; k0 < K; k0 += 8) {
        __syncthreads();
        As[ca + 0][ra] = av.x; As[ca + 1][ra] = av.y;
        As[ca + 2][ra] = av.z; As[ca + 3][ra] = av.w;
        Ws[cw + 0][rw] = wv.x; Ws[cw + 1][rw] = wv.y;
        __syncthreads();
        if (k0 + 8 < K) {
            int kn = k0 + 8;
            float4 a0 = *(const float4*)(p0 + kn);
            float4 a1 = *(const float4*)(p0 + pq + kn);
            float4 a2 = *(const float4*)(p0 + 2 * pq + kn);
            float4 a3 = *(const float4*)(p0 + 3 * pq + kn);
            bb = *(const float4*)(pb + kn);
            av.x = a0.x + a1.x + a2.x + a3.x + bb.x;
            av.y = a0.y + a1.y + a2.y + a3.y + bb.y;
            av.z = a0.z + a1.z + a2.z + a3.z + bb.z;
            av.w = a0.w + a1.w + a2.w + a3.w + bb.w;
            if (pt) {
                float4 tv = *(const float4*)(pt + kn);
                av.x += tv.x; av.y += tv.y; av.z += tv.z; av.w += tv.w;
            }
            av.x = fmaxf(av.x, 0.f); av.y = fmaxf(av.y, 0.f);
            av.z = fmaxf(av.z, 0.f); av.w = fmaxf(av.w, 0.f);
            wv = *(const float2*)(pw + kn);
        }
        mmstep(acc, As, Ws, tx, ty);
    }
}

// C pre-offset to (m0, n0)
__device__ __forceinline__ void store128(float* C, int ldc, float (&acc)[8][4]) {
    const int tx = threadIdx.x & 15, ty = threadIdx.x >> 4;
#pragma unroll
    for (int i = 0; i < 8; i++) {
        float4 v = make_float4(acc[i][0], acc[i][1], acc[i][2], acc[i][3]);
        *(float4*)(C + (size_t)(ty * 8 + i) * ldc + tx * 4) = v;
    }
}

// ======================================================================
// OLD 64x64 engine (kept for prologue / epilogue: M=64 strips, tiny GEMMs)
// ======================================================================
__device__ __forceinline__ void mm64(
    const float* __restrict__ A, int lda,
    const float* __restrict__ W, int ldw,
    int K, int m0, int n0w,
    float (&acc)[4][4],
    float (*As)[68], float (*Ws)[68])
{
    const int tid = threadIdx.x;
    const int lr = tid >> 2, lc = (tid & 3) << 2;
    const int tx = tid & 15, ty = tid >> 4;
    const float* pa = A + (size_t)(m0 + lr) * lda + lc;
    const float* pw = W + (size_t)(n0w + lr) * ldw + lc;
    float4 av = *(const float4*)pa;
    float4 wv = *(const float4*)pw;
    for (int k0 = 0; k0 < K; k0 += 16) {
        __syncthreads();
        As[lc + 0][lr] = av.x; As[lc + 1][lr] = av.y;
        As[lc + 2][lr] = av.z; As[lc + 3][lr] = av.w;
        Ws[lc + 0][lr] = wv.x; Ws[lc + 1][lr] = wv.y;
        Ws[lc + 2][lr] = wv.z; Ws[lc + 3][lr] = wv.w;
        __syncthreads();
        if (k0 + 16 < K) {
            av = *(const float4*)(pa + k0 + 16);
            wv = *(const float4*)(pw + k0 + 16);
        }
#pragma unroll
        for (int k = 0; k < 16; k++) {
            float4 a = *(const float4*)&As[k][ty << 2];
            float4 b = *(const float4*)&Ws[k][tx << 2];
            acc[0][0] += a.x * b.x; acc[0][1] += a.x * b.y; acc[0][2] += a.x * b.z; acc[0][3] += a.x * b.w;
            acc[1][0] += a.y * b.x; acc[1][1] += a.y * b.y; acc[1][2] += a.y * b.z; acc[1][3] += a.y * b.w;
            acc[2][0] += a.z * b.x; acc[2][1] += a.z * b.y; acc[2][2] += a.z * b.z; acc[2][3] += a.z * b.w;
            acc[3][0] += a.w * b.x; acc[3][1] += a.w * b.y; acc[3][2] += a.w * b.z; acc[3][3] += a.w * b.w;
        }
    }
}

__device__ __forceinline__ void store_plain(float* C, int ldc, float (&acc)[4][4]) {
    const int tx = threadIdx.x & 15, ty = threadIdx.x >> 4;
#pragma unroll
    for (int i = 0; i < 4; i++) {
        float4 v = make_float4(acc[i][0], acc[i][1], acc[i][2], acc[i][3]);
        *(float4*)(C + (size_t)(ty * 4 + i) * ldc + tx * 4) = v;
    }
}
__device__ __forceinline__ void store_epi(float* C, int ldc, float (&acc)[4][4],
                                          const float* __restrict__ bias, int relu) {
    const int tx = threadIdx.x & 15, ty = threadIdx.x >> 4;
    float4 bb = *(const float4*)(bias + tx * 4);
#pragma unroll
    for (int i = 0; i < 4; i++) {
        float4 v = make_float4(acc[i][0] + bb.x, acc[i][1] + bb.y,
                               acc[i][2] + bb.z, acc[i][3] + bb.w);
        if (relu) {
            v.x = fmaxf(v.x, 0.f); v.y = fmaxf(v.y, 0.f);
            v.z = fmaxf(v.z, 0.f); v.w = fmaxf(v.w, 0.f);
        }
        *(float4*)(C + (size_t)(ty * 4 + i) * ldc + tx * 4) = v;
    }
}

// ---------------- the one persistent kernel ----------------
__global__ void __launch_bounds__(256, 1) vrnn_persistent(
    const int* __restrict__ x, const float* __restrict__ h0,
    const float* __restrict__ eps,
    const float* __restrict__ phi_x_w, const float* __restrict__ phi_x_b,
    const float* __restrict__ enc_w1, const float* __restrict__ enc_b1,
    const float* __restrict__ enc_w2, const float* __restrict__ enc_b2,
    const float* __restrict__ pri_w1, const float* __restrict__ pri_b1,
    const float* __restrict__ pri_w2, const float* __restrict__ pri_b2,
    const float* __restrict__ phi_z_w, const float* __restrict__ phi_z_b,
    const float* __restrict__ dec_w, const float* __restrict__ dec_b,
    const float* __restrict__ act_w, const float* __restrict__ act_b,
    const float* __restrict__ wih, const float* __restrict__ whh,
    const float* __restrict__ bih, const float* __restrict__ bhh,
    float* __restrict__ out, int out_size)
{
    __shared__ float As8[8][132], Ws8[8][68];
    __shared__ float As[16][68], Ws[16][68];
    __shared__ int sJob;
    __shared__ double sRed[8];

    const int tid = threadIdx.x;
    const int gtid = blockIdx.x * blockDim.x + tid;
    const int nthr = gridDim.x * blockDim.x;
    double kacc = 0.0;

    // ---- P0: PX table ----
    for (int i = gtid; i < Avv * Hv; i += nthr) {
        int a = i >> 10, j = i & 1023;
        g_PX[i] = fmaxf(phi_x_w[(size_t)j * Avv + a] + phi_x_b[j], 0.f);
    }
    grid_sync();

    // ---- P1: ENCX (16) + GIX (48) tiles, mm64, K=1024 ----
    for (;;) {
        int j = next_job(&sJob);
        if (j >= 64) break;
        float acc[4][4] = {};
        if (j < 16) {
            mm64(g_PX, Hv, enc_w1 + (size_t)j * 64 * 2048, 2048, Hv, 0, 0, acc, As, Ws);
            store_plain(g_ENCX + j * 64, Hv, acc);
        } else {
            int nb = j - 16;
            mm64(g_PX, Hv, wih + (size_t)nb * 64 * 2048, 2048, Hv, 0, 0, acc, As, Ws);
            store_plain(g_GIX + nb * 64, H3, acc);
        }
    }
    grid_sync();

    // ================= recurrent steps =================
    for (int t = 0; t < Sv; t++) {
        const float* hcur = (t == 0) ? h0 : g_hbuf[(t + 1) & 1];
        float* hnext = g_hbuf[t & 1];

        // ---- Ph1: enc partials (128) | pri partials (128), K=256 each ----
        for (;;) {
            int j = next_job(&sJob);
            if (j >= 256) break;
            float acc[8][4] = {};
            int r = j & 127;
            int ks = r & 3, nb = (r >> 2) & 15, mb = (r >> 6) & 1;
            if (j < 128) {
                mm128(hcur + (size_t)mb * 128 * Hv + ks * 256, Hv,
                      enc_w1 + (size_t)nb * 64 * 2048 + 1024 + ks * 256, 2048,
                      256, acc, As8, Ws8);
                store128(g_h1encp[ks] + (size_t)mb * 128 * Hv + nb * 64, Hv, acc);
            } else {
                mm128(hcur + (size_t)mb * 128 * Hv + ks * 256, Hv,
                      pri_w1 + (size_t)nb * 64 * Hv + ks * 256, Hv,
                      256, acc, As8, Ws8);
                store128(g_h1prip[ks] + (size_t)mb * 128 * Hv + nb * 64, Hv, acc);
            }
        }
        grid_sync();

        // ---- Ph2: gh (ks 0,1: 192 jobs, big) + heads (128 jobs) ----
        for (;;) {
            int j = next_job(&sJob);
            if (j >= 320) break;
            float acc[8][4] = {};
            if (j < 192) {
                int ks = j & 1, mb = (j >> 1) & 1, nb = j >> 2;
                mm128(hcur + (size_t)mb * 128 * Hv + ks * 256, Hv,
                      whh + (size_t)nb * 64 * Hv + ks * 256, Hv,
                      256, acc, As8, Ws8);
                store128(g_ghp[ks] + (size_t)mb * 128 * H3 + nb * 64, H3, acc);
            } else {
                int q = j - 192;
                int ks = q & 7, zb = (q >> 3) & 3, mb = (q >> 5) & 1, typ = (q >> 6) & 1;
                int m0 = mb * 128, kofs = ks * 128;
                if (typ == 0) {
                    mm128_head(g_h1encp[0] + (size_t)m0 * Hv + kofs,
                               enc_b1 + kofs, g_ENCX + kofs, x + (size_t)m0 * Sv + t,
                               enc_w2 + (size_t)zb * 64 * Hv + kofs, Hv,
                               128, acc, As8, Ws8);
                    store128(g_hdencp[ks] + (size_t)m0 * Zv + zb * 64, Zv, acc);
                } else {
                    mm128_head(g_h1prip[0] + (size_t)m0 * Hv + kofs,
                               pri_b1 + kofs, nullptr, nullptr,
                               pri_w2 + (size_t)zb * 64 * Hv + kofs, Hv,
                               128, acc, As8, Ws8);
                    store128(g_hdprip[ks] + (size_t)m0 * Zv + zb * 64, Zv, acc);
                }
            }
        }
        grid_sync();

        // ---- Ph3: softplus + KLD + z ----
        {
            const float* ep = eps + (size_t)t * Bv * Zv;
            for (int i = gtid; i < Bv * Zv; i += nthr) {
                int zc = i & 255;
                float e = enc_b2[zc], p = pri_b2[zc];
#pragma unroll
                for (int q = 0; q < KS2; q++) { e += g_hdencp[q][i]; p += g_hdprip[q][i]; }
                float es = softplusf(e), ps = softplusf(p);
                float d = e - p;
                kacc += (double)(2.f * (logf(ps) - logf(es))
                                 + (es * es + d * d) / (ps * ps) - 1.f);
                g_zbuf[i] = ep[i] * es + e;
            }
        }
        grid_sync();

        // ---- Ph4: gh (ks 2,3: 192 jobs, big) + pz partials (128 jobs K=64) ----
        for (;;) {
            int j = next_job(&sJob);
            if (j >= 320) break;
            float acc[8][4] = {};
            if (j < 192) {
                int ks = 2 + (j & 1), mb = (j >> 1) & 1, nb = j >> 2;
                mm128(hcur + (size_t)mb * 128 * Hv + ks * 256, Hv,
                      whh + (size_t)nb * 64 * Hv + ks * 256, Hv,
                      256, acc, As8, Ws8);
                store128(g_ghp[ks] + (size_t)mb * 128 * H3 + nb * 64, H3, acc);
            } else {
                int q = j - 192;
                int ks = q & 3, nb = (q >> 2) & 15, mb = (q >> 6) & 1;
                mm128(g_zbuf + (size_t)mb * 128 * Zv + ks * 64, Zv,
                      phi_z_w + (size_t)nb * 64 * Zv + ks * 64, Zv,
                      64, acc, As8, Ws8);
                store128(g_pzp[ks] + (size_t)mb * 128 * Hv + nb * 64, Hv, acc);
            }
        }
        grid_sync();

        // ---- Ph5: gi = relu(sum pzp + b) @ wihR^T  (384 jobs K=256) ----
        for (;;) {
            int j = next_job(&sJob);
            if (j >= 384) break;
            float acc[8][4] = {};
            int ks = j & 3, nb = (j >> 2) % 48, mb = j / 192;
            int m0 = mb * 128, kofs = ks * 256;
            mm128_head(g_pzp[0] + (size_t)m0 * Hv + kofs,
                       phi_z_b + kofs, nullptr, nullptr,
                       wih + (size_t)nb * 64 * 2048 + 1024 + kofs, 2048,
                       256, acc, As8, Ws8);
            store128(g_gip[ks] + (size_t)m0 * H3 + nb * 64, H3, acc);
        }
        grid_sync();

        // ---- Ph6: GRU gates ----
        for (int i = gtid; i < Bv * Hv; i += nthr) {
            int m = i >> 10, j = i & 1023;
            int xm = x[(size_t)m * Sv + t];
            size_t b3 = (size_t)m * H3;
            size_t tb = (size_t)xm * H3;
            float gr = bih[j] + g_GIX[tb + j];
            float gz = bih[Hv + j] + g_GIX[tb + Hv + j];
            float gn = bih[2 * Hv + j] + g_GIX[tb + 2 * Hv + j];
            float hr = bhh[j], hz = bhh[Hv + j], hn = bhh[2 * Hv + j];
#pragma unroll
            for (int q = 0; q < KS1; q++) {
                gr += g_gip[q][b3 + j];          hr += g_ghp[q][b3 + j];
                gz += g_gip[q][b3 + Hv + j];     hz += g_ghp[q][b3 + Hv + j];
                gn += g_gip[q][b3 + 2 * Hv + j]; hn += g_ghp[q][b3 + 2 * Hv + j];
            }
            float r = sigmoidf(gr + hr);
            float zg = sigmoidf(gz + hz);
            float n = tanhf(gn + r * hn);
            hnext[i] = (1.f - zg) * n + zg * hcur[i];
        }
        grid_sync();
    }

    // ================= epilogue (mm64 path, one-time) =================
    const float* hF = g_hbuf[1];

    for (;;) {
        int j = next_job(&sJob);
        if (j >= 64) break;
        float acc[4][4] = {};
        int mb = j >> 4, nb = j & 15;
        mm64(hF + (size_t)mb * 64 * Hv, Hv,
             pri_w1 + (size_t)nb * 64 * Hv, Hv, Hv, 0, 0, acc, As, Ws);
        store_epi(g_fh1 + (size_t)mb * 64 * Hv + nb * 64, Hv, acc, pri_b1 + nb * 64, 1);
    }
    grid_sync();

    for (;;) {
        int j = next_job(&sJob);
        if (j >= 16) break;
        float acc[4][4] = {};
        int mb = j >> 2, nb = j & 3;
        mm64(g_fh1 + (size_t)mb * 64 * Hv, Hv,
             pri_w2 + (size_t)nb * 64 * Hv, Hv, Hv, 0, 0, acc, As, Ws);
        store_epi(g_fpri + (size_t)mb * 64 * Zv + nb * 64, Zv, acc, pri_b2 + nb * 64, 0);
    }
    grid_sync();

    {
        const float* ep = eps + (size_t)Sv * Bv * Zv;
        for (int i = gtid; i < Bv * Zv; i += nthr) {
            float p = g_fpri[i];
            g_zbuf[i] = ep[i] * softplusf(p) + p;
        }
    }
    grid_sync();

    for (;;) {
        int j = next_job(&sJob);
        if (j >= 64) break;
        float acc[4][4] = {};
        int mb = j >> 4, nb = j & 15;
        mm64(g_zbuf + (size_t)mb * 64 * Zv, Zv,
             phi_z_w + (size_t)nb * 64 * Zv, Zv, Zv, 0, 0, acc, As, Ws);
        store_epi(g_pz + (size_t)mb * 64 * Hv + nb * 64, Hv, acc, phi_z_b + nb * 64, 1);
    }
    grid_sync();

    for (;;) {
        int j = next_job(&sJob);
        if (j >= 64) break;
        float acc[4][4] = {};
        int mb = j >> 4, nb = j & 15;
        mm64(g_pz + (size_t)mb * 64 * Hv, Hv,
             dec_w + (size_t)nb * 64 * 2048, 2048, Hv, 0, 0, acc, As, Ws);
        mm64(hF + (size_t)mb * 64 * Hv, Hv,
             dec_w + (size_t)nb * 64 * 2048 + 1024, 2048, Hv, 0, 0, acc, As, Ws);
        store_epi(g_decb + (size_t)mb * 64 * Hv + nb * 64, Hv, acc, dec_b + nb * 64, 1);
    }
    grid_sync();

    for (;;) {
        int j = next_job(&sJob);
        if (j >= 4) break;
        float acc[4][4] = {};
        mm64(g_decb + (size_t)j * 64 * Hv, Hv, act_w, Hv, Hv, 0, 0, acc, As, Ws);
        store_epi(out + (size_t)j * 64 * Avv, Avv, acc, act_b, 0);
    }
    {
        double v = kacc;
#pragma unroll
        for (int off = 16; off > 0; off >>= 1)
            v += __shfl_down_sync(0xffffffffu, v, off);
        if ((tid & 31) == 0) sRed[tid >> 5] = v;
        __syncthreads();
        if (tid == 0) {
            double s = 0.0;
            for (int w = 0; w < 8; w++) s += sRed[w];
            g_kldp[blockIdx.x] = s;
        }
    }
    grid_sync();

    if (blockIdx.x == 0 && tid == 0) {
        double s = 0.0;
        for (unsigned b = 0; b < gridDim.x; b++) s += g_kldp[b];
        out[out_size - 1] = (float)(0.5 * s);
    }
}

// ---------------- host launch: ONE kernel node ----------------
extern "C" void kernel_launch(void* const* d_in, const int* in_sizes, int n_in,
                              void* d_out, int out_size)
{
    int dev = 0;
    cudaGetDevice(&dev);
    int sms = 0;
    cudaDeviceGetAttribute(&sms, cudaDevAttrMultiProcessorCount, dev);
    if (sms < 1) sms = 148;
    if (sms > 1024) sms = 1024;

    vrnn_persistent<<<sms, 256>>>(
        (const int*)d_in[0], (const float*)d_in[1], (const float*)d_in[2],
        (const float*)d_in[3], (const float*)d_in[4],
        (const float*)d_in[5], (const float*)d_in[6],
        (const float*)d_in[7], (const float*)d_in[8],
        (const float*)d_in[9], (const float*)d_in[10],
        (const float*)d_in[11], (const float*)d_in[12],
        (const float*)d_in[13], (const float*)d_in[14],
        (const float*)d_in[15], (const float*)d_in[16],
        (const float*)d_in[17], (const float*)d_in[18],
        (const float*)d_in[19], (const float*)d_in[20],
        (const float*)d_in[21], (const float*)d_in[22],
        (float*)d_out, out_size);
}

// round 7
// speedup vs baseline: 1.0023x; 1.0023x over previous
#include <cuda_runtime.h>
#include <math.h>

#define Bv 256
#define Sv 512
#define Avv 64
#define Hv 1024
#define Zv 256
#define H3 3072
#define KS1 4
#define KS2 8

// ---------------- device scratch (static: no allocations) ----------------
__device__ float g_hbuf[2][Bv * Hv];
__device__ float g_PX[Avv * Hv];
__device__ float g_ENCX[Avv * Hv];
__device__ float g_GIX[Avv * H3];
__device__ float g_h1encp[KS1][Bv * Hv];
__device__ float g_h1prip[KS1][Bv * Hv];
__device__ float g_ghp[KS1][Bv * H3];
__device__ float g_gip[KS1][Bv * H3];
__device__ float g_pzp[KS1][Bv * Hv];
__device__ float g_hdencp[KS2][Bv * Zv];
__device__ float g_hdprip[KS2][Bv * Zv];
__device__ float g_zbuf[Bv * Zv];
__device__ float g_pz[Bv * Hv];
__device__ float g_fh1[Bv * Hv];
__device__ float g_fpri[Bv * Zv];
__device__ float g_decb[Bv * Hv];
__device__ double g_kldp[1024];
__device__ unsigned g_arrive, g_release, g_work;

// ---------------- helpers ----------------
__device__ __forceinline__ float softplusf(float x) {
    return x > 0.f ? x + log1pf(expf(-x)) : log1pf(expf(x));
}
__device__ __forceinline__ float sigmoidf(float x) {
    return 1.f / (1.f + expf(-x));
}

__device__ __forceinline__ void grid_sync() {
    __syncthreads();
    if (threadIdx.x == 0) {
        __threadfence();
        volatile unsigned* rel = &g_release;
        unsigned gen = *rel;
        if (atomicAdd(&g_arrive, 1u) == gridDim.x - 1u) {
            g_arrive = 0u;
            g_work = 0u;
            __threadfence();
            atomicAdd(&g_release, 1u);
        } else {
            while (*rel == gen) __nanosleep(32);
        }
    }
    __syncthreads();
    __threadfence();
}

__device__ __forceinline__ int next_job(int* sJob) {
    __syncthreads();
    if (threadIdx.x == 0) *sJob = (int)atomicAdd(&g_work, 1u);
    __syncthreads();
    return *sJob;
}

// ======================================================================
// NEW engine: 128x64 tile, 256 threads, 8x4 thread tile, BK=8.
// As[8][132] transposed (As[k][m]); Ws[8][68] transposed (Ws[k][n]).
// acc[i][j]: row ty*8+i, col tx*4+j  (tx=tid&15, ty=tid>>4)
// ======================================================================
__device__ __forceinline__ void mmstep(
    float (&acc)[8][4], const float (*As)[132], const float (*Ws)[68],
    int tx, int ty)
{
#pragma unroll
    for (int k = 0; k < 8; k++) {
        float4 a0 = *(const float4*)&As[k][ty * 8];
        float4 a1 = *(const float4*)&As[k][ty * 8 + 4];
        float4 b  = *(const float4*)&Ws[k][tx * 4];
        acc[0][0] += a0.x * b.x; acc[0][1] += a0.x * b.y; acc[0][2] += a0.x * b.z; acc[0][3] += a0.x * b.w;
        acc[1][0] += a0.y * b.x; acc[1][1] += a0.y * b.y; acc[1][2] += a0.y * b.z; acc[1][3] += a0.y * b.w;
        acc[2][0] += a0.z * b.x; acc[2][1] += a0.z * b.y; acc[2][2] += a0.z * b.z; acc[2][3] += a0.z * b.w;
        acc[3][0] += a0.w * b.x; acc[3][1] += a0.w * b.y; acc[3][2] += a0.w * b.z; acc[3][3] += a0.w * b.w;
        acc[4][0] += a1.x * b.x; acc[4][1] += a1.x * b.y; acc[4][2] += a1.x * b.z; acc[4][3] += a1.x * b.w;
        acc[5][0] += a1.y * b.x; acc[5][1] += a1.y * b.y; acc[5][2] += a1.y * b.z; acc[5][3] += a1.y * b.w;
        acc[6][0] += a1.z * b.x; acc[6][1] += a1.z * b.y; acc[6][2] += a1.z * b.z; acc[6][3] += a1.z * b.w;
        acc[7][0] += a1.w * b.x; acc[7][1] += a1.w * b.y; acc[7][2] += a1.w * b.z; acc[7][3] += a1.w * b.w;
    }
}

// plain: A[128,K] row-major (lda), W[64,K] row-major (ldw)
__device__ __forceinline__ void mm128(
    const float* __restrict__ A, int lda,
    const float* __restrict__ W, int ldw,
    int K, float (&acc)[8][4],
    float (*As)[132], float (*Ws)[68])
{
    const int tid = threadIdx.x;
    const int ra = tid >> 1, ca = (tid & 1) * 4;   // A staging: row, col-group
    const int rw = tid >> 2, cw = (tid & 3) * 2;   // W staging
    const int tx = tid & 15, ty = tid >> 4;
    const float* pa = A + (size_t)ra * lda + ca;
    const float* pw = W + (size_t)rw * ldw + cw;
    float4 av = *(const float4*)pa;
    float2 wv = *(const float2*)pw;
    for (int k0 = 0; k0 < K; k0 += 8) {
        __syncthreads();
        As[ca + 0][ra] = av.x; As[ca + 1][ra] = av.y;
        As[ca + 2][ra] = av.z; As[ca + 3][ra] = av.w;
        Ws[cw + 0][rw] = wv.x; Ws[cw + 1][rw] = wv.y;
        __syncthreads();
        if (k0 + 8 < K) {
            av = *(const float4*)(pa + k0 + 8);
            wv = *(const float2*)(pw + k0 + 8);
        }
        mmstep(acc, As, Ws, tx, ty);
    }
}

// head: A row r, col c built = relu(sum_{q<4} P[q][r,c] + b1[c] (+ tab[x[r]][c]))
// P base pre-offset (m0*Hv + kofs), row stride Hv, partial stride pq=Bv*Hv.
// b1 pre-offset (+kofs); tab pre-offset (+kofs) or null; xc = x + m0*Sv + t.
__device__ __forceinline__ void mm128_head(
    const float* __restrict__ P,
    const float* __restrict__ b1,
    const float* __restrict__ tab, const int* __restrict__ xc,
    const float* __restrict__ W, int ldw,
    int K, float (&acc)[8][4],
    float (*As)[132], float (*Ws)[68])
{
    const int tid = threadIdx.x;
    const int ra = tid >> 1, ca = (tid & 1) * 4;
    const int rw = tid >> 2, cw = (tid & 3) * 2;
    const int tx = tid & 15, ty = tid >> 4;
    const size_t pq = (size_t)Bv * Hv;
    const float* p0 = P + (size_t)ra * Hv + ca;
    const float* pw = W + (size_t)rw * ldw + cw;
    const float* pt = tab ? (tab + (size_t)xc[ra * Sv] * Hv + ca) : nullptr;
    const float* pb = b1 + ca;

    float4 av, bb;
    float2 wv;
    {
        float4 a0 = *(const float4*)(p0);
        float4 a1 = *(const float4*)(p0 + pq);
        float4 a2 = *(const float4*)(p0 + 2 * pq);
        float4 a3 = *(const float4*)(p0 + 3 * pq);
        bb = *(const float4*)(pb);
        av.x = a0.x + a1.x + a2.x + a3.x + bb.x;
        av.y = a0.y + a1.y + a2.y + a3.y + bb.y;
        av.z = a0.z + a1.z + a2.z + a3.z + bb.z;
        av.w = a0.w + a1.w + a2.w + a3.w + bb.w;
        if (pt) {
            float4 tv = *(const float4*)(pt);
            av.x += tv.x; av.y += tv.y; av.z += tv.z; av.w += tv.w;
        }
        av.x = fmaxf(av.x, 0.f); av.y = fmaxf(av.y, 0.f);
        av.z = fmaxf(av.z, 0.f); av.w = fmaxf(av.w, 0.f);
        wv = *(const float2*)pw;
    }
    for (int k0 = 0; k0 < K; k0 += 8) {
        __syncthreads();
        As[ca + 0][ra] = av.x; As[ca + 1][ra] = av.y;
        As[ca + 2][ra] = av.z; As[ca + 3][ra] = av.w;
        Ws[cw + 0][rw] = wv.x; Ws[cw + 1][rw] = wv.y;
        __syncthreads();
        if (k0 + 8 < K) {
            int kn = k0 + 8;
            float4 a0 = *(const float4*)(p0 + kn);
            float4 a1 = *(const float4*)(p0 + pq + kn);
            float4 a2 = *(const float4*)(p0 + 2 * pq + kn);
            float4 a3 = *(const float4*)(p0 + 3 * pq + kn);
            bb = *(const float4*)(pb + kn);
            av.x = a0.x + a1.x + a2.x + a3.x + bb.x;
            av.y = a0.y + a1.y + a2.y + a3.y + bb.y;
            av.z = a0.z + a1.z + a2.z + a3.z + bb.z;
            av.w = a0.w + a1.w + a2.w + a3.w + bb.w;
            if (pt) {
                float4 tv = *(const float4*)(pt + kn);
                av.x += tv.x; av.y += tv.y; av.z += tv.z; av.w += tv.w;
            }
            av.x = fmaxf(av.x, 0.f); av.y = fmaxf(av.y, 0.f);
            av.z = fmaxf(av.z, 0.f); av.w = fmaxf(av.w, 0.f);
            wv = *(const float2*)(pw + kn);
        }
        mmstep(acc, As, Ws, tx, ty);
    }
}

// C pre-offset to (m0, n0)
__device__ __forceinline__ void store128(float* C, int ldc, float (&acc)[8][4]) {
    const int tx = threadIdx.x & 15, ty = threadIdx.x >> 4;
#pragma unroll
    for (int i = 0; i < 8; i++) {
        float4 v = make_float4(acc[i][0], acc[i][1], acc[i][2], acc[i][3]);
        *(float4*)(C + (size_t)(ty * 8 + i) * ldc + tx * 4) = v;
    }
}

// ======================================================================
// OLD 64x64 engine (kept for prologue / epilogue: M=64 strips, tiny GEMMs)
// ======================================================================
__device__ __forceinline__ void mm64(
    const float* __restrict__ A, int lda,
    const float* __restrict__ W, int ldw,
    int K, int m0, int n0w,
    float (&acc)[4][4],
    float (*As)[68], float (*Ws)[68])
{
    const int tid = threadIdx.x;
    const int lr = tid >> 2, lc = (tid & 3) << 2;
    const int tx = tid & 15, ty = tid >> 4;
    const float* pa = A + (size_t)(m0 + lr) * lda + lc;
    const float* pw = W + (size_t)(n0w + lr) * ldw + lc;
    float4 av = *(const float4*)pa;
    float4 wv = *(const float4*)pw;
    for (int k0 = 0; k0 < K; k0 += 16) {
        __syncthreads();
        As[lc + 0][lr] = av.x; As[lc + 1][lr] = av.y;
        As[lc + 2][lr] = av.z; As[lc + 3][lr] = av.w;
        Ws[lc + 0][lr] = wv.x; Ws[lc + 1][lr] = wv.y;
        Ws[lc + 2][lr] = wv.z; Ws[lc + 3][lr] = wv.w;
        __syncthreads();
        if (k0 + 16 < K) {
            av = *(const float4*)(pa + k0 + 16);
            wv = *(const float4*)(pw + k0 + 16);
        }
#pragma unroll
        for (int k = 0; k < 16; k++) {
            float4 a = *(const float4*)&As[k][ty << 2];
            float4 b = *(const float4*)&Ws[k][tx << 2];
            acc[0][0] += a.x * b.x; acc[0][1] += a.x * b.y; acc[0][2] += a.x * b.z; acc[0][3] += a.x * b.w;
            acc[1][0] += a.y * b.x; acc[1][1] += a.y * b.y; acc[1][2] += a.y * b.z; acc[1][3] += a.y * b.w;
            acc[2][0] += a.z * b.x; acc[2][1] += a.z * b.y; acc[2][2] += a.z * b.z; acc[2][3] += a.z * b.w;
            acc[3][0] += a.w * b.x; acc[3][1] += a.w * b.y; acc[3][2] += a.w * b.z; acc[3][3] += a.w * b.w;
        }
    }
}

__device__ __forceinline__ void store_plain(float* C, int ldc, float (&acc)[4][4]) {
    const int tx = threadIdx.x & 15, ty = threadIdx.x >> 4;
#pragma unroll
    for (int i = 0; i < 4; i++) {
        float4 v = make_float4(acc[i][0], acc[i][1], acc[i][2], acc[i][3]);
        *(float4*)(C + (size_t)(ty * 4 + i) * ldc + tx * 4) = v;
    }
}
__device__ __forceinline__ void store_epi(float* C, int ldc, float (&acc)[4][4],
                                          const float* __restrict__ bias, int relu) {
    const int tx = threadIdx.x & 15, ty = threadIdx.x >> 4;
    float4 bb = *(const float4*)(bias + tx * 4);
#pragma unroll
    for (int i = 0; i < 4; i++) {
        float4 v = make_float4(acc[i][0] + bb.x, acc[i][1] + bb.y,
                               acc[i][2] + bb.z, acc[i][3] + bb.w);
        if (relu) {
            v.x = fmaxf(v.x, 0.f); v.y = fmaxf(v.y, 0.f);
            v.z = fmaxf(v.z, 0.f); v.w = fmaxf(v.w, 0.f);
        }
        *(float4*)(C + (size_t)(ty * 4 + i) * ldc + tx * 4) = v;
    }
}

// ---------------- the one persistent kernel ----------------
__global__ void __launch_bounds__(256, 1) vrnn_persistent(
    const int* __restrict__ x, const float* __restrict__ h0,
    const float* __restrict__ eps,
    const float* __restrict__ phi_x_w, const float* __restrict__ phi_x_b,
    const float* __restrict__ enc_w1, const float* __restrict__ enc_b1,
    const float* __restrict__ enc_w2, const float* __restrict__ enc_b2,
    const float* __restrict__ pri_w1, const float* __restrict__ pri_b1,
    const float* __restrict__ pri_w2, const float* __restrict__ pri_b2,
    const float* __restrict__ phi_z_w, const float* __restrict__ phi_z_b,
    const float* __restrict__ dec_w, const float* __restrict__ dec_b,
    const float* __restrict__ act_w, const float* __restrict__ act_b,
    const float* __restrict__ wih, const float* __restrict__ whh,
    const float* __restrict__ bih, const float* __restrict__ bhh,
    float* __restrict__ out, int out_size)
{
    __shared__ float As8[8][132], Ws8[8][68];
    __shared__ float As[16][68], Ws[16][68];
    __shared__ int sJob;
    __shared__ double sRed[8];

    const int tid = threadIdx.x;
    const int gtid = blockIdx.x * blockDim.x + tid;
    const int nthr = gridDim.x * blockDim.x;
    double kacc = 0.0;

    // ---- P0: PX table ----
    for (int i = gtid; i < Avv * Hv; i += nthr) {
        int a = i >> 10, j = i & 1023;
        g_PX[i] = fmaxf(phi_x_w[(size_t)j * Avv + a] + phi_x_b[j], 0.f);
    }
    grid_sync();

    // ---- P1: ENCX (16) + GIX (48) tiles, mm64, K=1024 ----
    for (;;) {
        int j = next_job(&sJob);
        if (j >= 64) break;
        float acc[4][4] = {};
        if (j < 16) {
            mm64(g_PX, Hv, enc_w1 + (size_t)j * 64 * 2048, 2048, Hv, 0, 0, acc, As, Ws);
            store_plain(g_ENCX + j * 64, Hv, acc);
        } else {
            int nb = j - 16;
            mm64(g_PX, Hv, wih + (size_t)nb * 64 * 2048, 2048, Hv, 0, 0, acc, As, Ws);
            store_plain(g_GIX + nb * 64, H3, acc);
        }
    }
    grid_sync();

    // ================= recurrent steps =================
    for (int t = 0; t < Sv; t++) {
        const float* hcur = (t == 0) ? h0 : g_hbuf[(t + 1) & 1];
        float* hnext = g_hbuf[t & 1];

        // ---- Ph1: enc partials (128) | pri partials (128), K=256 each ----
        for (;;) {
            int j = next_job(&sJob);
            if (j >= 256) break;
            float acc[8][4] = {};
            int r = j & 127;
            int ks = r & 3, nb = (r >> 2) & 15, mb = (r >> 6) & 1;
            if (j < 128) {
                mm128(hcur + (size_t)mb * 128 * Hv + ks * 256, Hv,
                      enc_w1 + (size_t)nb * 64 * 2048 + 1024 + ks * 256, 2048,
                      256, acc, As8, Ws8);
                store128(g_h1encp[ks] + (size_t)mb * 128 * Hv + nb * 64, Hv, acc);
            } else {
                mm128(hcur + (size_t)mb * 128 * Hv + ks * 256, Hv,
                      pri_w1 + (size_t)nb * 64 * Hv + ks * 256, Hv,
                      256, acc, As8, Ws8);
                store128(g_h1prip[ks] + (size_t)mb * 128 * Hv + nb * 64, Hv, acc);
            }
        }
        grid_sync();

        // ---- Ph2: gh (ks 0,1: 192 jobs, big) + heads (128 jobs) ----
        for (;;) {
            int j = next_job(&sJob);
            if (j >= 320) break;
            float acc[8][4] = {};
            if (j < 192) {
                int ks = j & 1, mb = (j >> 1) & 1, nb = j >> 2;
                mm128(hcur + (size_t)mb * 128 * Hv + ks * 256, Hv,
                      whh + (size_t)nb * 64 * Hv + ks * 256, Hv,
                      256, acc, As8, Ws8);
                store128(g_ghp[ks] + (size_t)mb * 128 * H3 + nb * 64, H3, acc);
            } else {
                int q = j - 192;
                int ks = q & 7, zb = (q >> 3) & 3, mb = (q >> 5) & 1, typ = (q >> 6) & 1;
                int m0 = mb * 128, kofs = ks * 128;
                if (typ == 0) {
                    mm128_head(g_h1encp[0] + (size_t)m0 * Hv + kofs,
                               enc_b1 + kofs, g_ENCX + kofs, x + (size_t)m0 * Sv + t,
                               enc_w2 + (size_t)zb * 64 * Hv + kofs, Hv,
                               128, acc, As8, Ws8);
                    store128(g_hdencp[ks] + (size_t)m0 * Zv + zb * 64, Zv, acc);
                } else {
                    mm128_head(g_h1prip[0] + (size_t)m0 * Hv + kofs,
                               pri_b1 + kofs, nullptr, nullptr,
                               pri_w2 + (size_t)zb * 64 * Hv + kofs, Hv,
                               128, acc, As8, Ws8);
                    store128(g_hdprip[ks] + (size_t)m0 * Zv + zb * 64, Zv, acc);
                }
            }
        }
        grid_sync();

        // ---- Ph3: softplus + KLD + z ----
        {
            const float* ep = eps + (size_t)t * Bv * Zv;
            for (int i = gtid; i < Bv * Zv; i += nthr) {
                int zc = i & 255;
                float e = enc_b2[zc], p = pri_b2[zc];
#pragma unroll
                for (int q = 0; q < KS2; q++) { e += g_hdencp[q][i]; p += g_hdprip[q][i]; }
                float es = softplusf(e), ps = softplusf(p);
                float d = e - p;
                kacc += (double)(2.f * (logf(ps) - logf(es))
                                 + (es * es + d * d) / (ps * ps) - 1.f);
                g_zbuf[i] = ep[i] * es + e;
            }
        }
        grid_sync();

        // ---- Ph4: gh (ks 2,3: 192 jobs, big) + pz partials (128 jobs K=64) ----
        for (;;) {
            int j = next_job(&sJob);
            if (j >= 320) break;
            float acc[8][4] = {};
            if (j < 192) {
                int ks = 2 + (j & 1), mb = (j >> 1) & 1, nb = j >> 2;
                mm128(hcur + (size_t)mb * 128 * Hv + ks * 256, Hv,
                      whh + (size_t)nb * 64 * Hv + ks * 256, Hv,
                      256, acc, As8, Ws8);
                store128(g_ghp[ks] + (size_t)mb * 128 * H3 + nb * 64, H3, acc);
            } else {
                int q = j - 192;
                int ks = q & 3, nb = (q >> 2) & 15, mb = (q >> 6) & 1;
                mm128(g_zbuf + (size_t)mb * 128 * Zv + ks * 64, Zv,
                      phi_z_w + (size_t)nb * 64 * Zv + ks * 64, Zv,
                      64, acc, As8, Ws8);
                store128(g_pzp[ks] + (size_t)mb * 128 * Hv + nb * 64, Hv, acc);
            }
        }
        grid_sync();

        // ---- Ph5: gi = relu(sum pzp + b) @ wihR^T  (384 jobs K=256) ----
        for (;;) {
            int j = next_job(&sJob);
            if (j >= 384) break;
            float acc[8][4] = {};
            int ks = j & 3, nb = (j >> 2) % 48, mb = j / 192;
            int m0 = mb * 128, kofs = ks * 256;
            mm128_head(g_pzp[0] + (size_t)m0 * Hv + kofs,
                       phi_z_b + kofs, nullptr, nullptr,
                       wih + (size_t)nb * 64 * 2048 + 1024 + kofs, 2048,
                       256, acc, As8, Ws8);
            store128(g_gip[ks] + (size_t)m0 * H3 + nb * 64, H3, acc);
        }
        grid_sync();

        // ---- Ph6: GRU gates ----
        for (int i = gtid; i < Bv * Hv; i += nthr) {
            int m = i >> 10, j = i & 1023;
            int xm = x[(size_t)m * Sv + t];
            size_t b3 = (size_t)m * H3;
            size_t tb = (size_t)xm * H3;
            float gr = bih[j] + g_GIX[tb + j];
            float gz = bih[Hv + j] + g_GIX[tb + Hv + j];
            float gn = bih[2 * Hv + j] + g_GIX[tb + 2 * Hv + j];
            float hr = bhh[j], hz = bhh[Hv + j], hn = bhh[2 * Hv + j];
#pragma unroll
            for (int q = 0; q < KS1; q++) {
                gr += g_gip[q][b3 + j];          hr += g_ghp[q][b3 + j];
                gz += g_gip[q][b3 + Hv + j];     hz += g_ghp[q][b3 + Hv + j];
                gn += g_gip[q][b3 + 2 * Hv + j]; hn += g_ghp[q][b3 + 2 * Hv + j];
            }
            float r = sigmoidf(gr + hr);
            float zg = sigmoidf(gz + hz);
            float n = tanhf(gn + r * hn);
            hnext[i] = (1.f - zg) * n + zg * hcur[i];
        }
        grid_sync();
    }

    // ================= epilogue (mm64 path, one-time) =================
    const float* hF = g_hbuf[1];

    for (;;) {
        int j = next_job(&sJob);
        if (j >= 64) break;
        float acc[4][4] = {};
        int mb = j >> 4, nb = j & 15;
        mm64(hF + (size_t)mb * 64 * Hv, Hv,
             pri_w1 + (size_t)nb * 64 * Hv, Hv, Hv, 0, 0, acc, As, Ws);
        store_epi(g_fh1 + (size_t)mb * 64 * Hv + nb * 64, Hv, acc, pri_b1 + nb * 64, 1);
    }
    grid_sync();

    for (;;) {
        int j = next_job(&sJob);
        if (j >= 16) break;
        float acc[4][4] = {};
        int mb = j >> 2, nb = j & 3;
        mm64(g_fh1 + (size_t)mb * 64 * Hv, Hv,
             pri_w2 + (size_t)nb * 64 * Hv, Hv, Hv, 0, 0, acc, As, Ws);
        store_epi(g_fpri + (size_t)mb * 64 * Zv + nb * 64, Zv, acc, pri_b2 + nb * 64, 0);
    }
    grid_sync();

    {
        const float* ep = eps + (size_t)Sv * Bv * Zv;
        for (int i = gtid; i < Bv * Zv; i += nthr) {
            float p = g_fpri[i];
            g_zbuf[i] = ep[i] * softplusf(p) + p;
        }
    }
    grid_sync();

    for (;;) {
        int j = next_job(&sJob);
        if (j >= 64) break;
        float acc[4][4] = {};
        int mb = j >> 4, nb = j & 15;
        mm64(g_zbuf + (size_t)mb * 64 * Zv, Zv,
             phi_z_w + (size_t)nb * 64 * Zv, Zv, Zv, 0, 0, acc, As, Ws);
        store_epi(g_pz + (size_t)mb * 64 * Hv + nb * 64, Hv, acc, phi_z_b + nb * 64, 1);
    }
    grid_sync();

    for (;;) {
        int j = next_job(&sJob);
        if (j >= 64) break;
        float acc[4][4] = {};
        int mb = j >> 4, nb = j & 15;
        mm64(g_pz + (size_t)mb * 64 * Hv, Hv,
             dec_w + (size_t)nb * 64 * 2048, 2048, Hv, 0, 0, acc, As, Ws);
        mm64(hF + (size_t)mb * 64 * Hv, Hv,
             dec_w + (size_t)nb * 64 * 2048 + 1024, 2048, Hv, 0, 0, acc, As, Ws);
        store_epi(g_decb + (size_t)mb * 64 * Hv + nb * 64, Hv, acc, dec_b + nb * 64, 1);
    }
    grid_sync();

    for (;;) {
        int j = next_job(&sJob);
        if (j >= 4) break;
        float acc[4][4] = {};
        mm64(g_decb + (size_t)j * 64 * Hv, Hv, act_w, Hv, Hv, 0, 0, acc, As, Ws);
        store_epi(out + (size_t)j * 64 * Avv, Avv, acc, act_b, 0);
    }
    {
        double v = kacc;
#pragma unroll
        for (int off = 16; off > 0; off >>= 1)
            v += __shfl_down_sync(0xffffffffu, v, off);
        if ((tid & 31) == 0) sRed[tid >> 5] = v;
        __syncthreads();
        if (tid == 0) {
            double s = 0.0;
            for (int w = 0; w < 8; w++) s += sRed[w];
            g_kldp[blockIdx.x] = s;
        }
    }
    grid_sync();

    if (blockIdx.x == 0 && tid == 0) {
        double s = 0.0;
        for (unsigned b = 0; b < gridDim.x; b++) s += g_kldp[b];
        out[out_size - 1] = (float)(0.5 * s);
    }
}

// ---------------- host launch: ONE kernel node ----------------
extern "C" void kernel_launch(void* const* d_in, const int* in_sizes, int n_in,
                              void* d_out, int out_size)
{
    int dev = 0;
    cudaGetDevice(&dev);
    int sms = 0;
    cudaDeviceGetAttribute(&sms, cudaDevAttrMultiProcessorCount, dev);
    if (sms < 1) sms = 148;
    if (sms > 1024) sms = 1024;

    vrnn_persistent<<<sms, 256>>>(
        (const int*)d_in[0], (const float*)d_in[1], (const float*)d_in[2],
        (const float*)d_in[3], (const float*)d_in[4],
        (const float*)d_in[5], (const float*)d_in[6],
        (const float*)d_in[7], (const float*)d_in[8],
        (const float*)d_in[9], (const float*)d_in[10],
        (const float*)d_in[11], (const float*)d_in[12],
        (const float*)d_in[13], (const float*)d_in[14],
        (const float*)d_in[15], (const float*)d_in[16],
        (const float*)d_in[17], (const float*)d_in[18],
        (const float*)d_in[19], (const float*)d_in[20],
        (const float*)d_in[21], (const float*)d_in[22],
        (float*)d_out, out_size);
}

// round 12
// speedup vs baseline: 1.0505x; 1.0480x over previous
#include <cuda_runtime.h>
#include <math.h>

#define Bv 256
#define Sv 512
#define Avv 64
#define Hv 1024
#define Zv 256
#define H3 3072
#define KS1 4
#define KS2 8

// ---------------- device scratch (static: no allocations) ----------------
__device__ float g_hbuf[2][Bv * Hv];
__device__ float g_PX[Avv * Hv];
__device__ float g_ENCX[Avv * Hv];
__device__ float g_GIX[Avv * H3];
__device__ float g_h1encp[KS1][Bv * Hv];
__device__ float g_h1prip[KS1][Bv * Hv];
__device__ float g_ghp[KS1][Bv * H3];
__device__ float g_gip[KS1][Bv * H3];
__device__ float g_pzp[KS1][Bv * Hv];
__device__ float g_hdencp[KS2][Bv * Zv];
__device__ float g_hdprip[KS2][Bv * Zv];
__device__ float g_zbuf[Bv * Zv];
__device__ float g_pz[Bv * Hv];
__device__ float g_fh1[Bv * Hv];
__device__ float g_fpri[Bv * Zv];
__device__ float g_decb[Bv * Hv];
__device__ double g_kldp[1024];
__device__ unsigned g_arrive, g_release, g_work;

// ---------------- helpers ----------------
__device__ __forceinline__ float softplusf(float x) {
    return x > 0.f ? x + log1pf(expf(-x)) : log1pf(expf(x));
}
__device__ __forceinline__ float sigmoidf(float x) {
    return 1.f / (1.f + expf(-x));
}

__device__ __forceinline__ void grid_sync() {
    __syncthreads();
    if (threadIdx.x == 0) {
        __threadfence();
        volatile unsigned* rel = &g_release;
        unsigned gen = *rel;
        if (atomicAdd(&g_arrive, 1u) == gridDim.x - 1u) {
            g_arrive = 0u;
            g_work = 0u;
            __threadfence();
            atomicAdd(&g_release, 1u);
        } else {
            while (*rel == gen) __nanosleep(32);
        }
    }
    __syncthreads();
    __threadfence();
}

__device__ __forceinline__ int next_job(int* sJob) {
    __syncthreads();
    if (threadIdx.x == 0) *sJob = (int)atomicAdd(&g_work, 1u);
    __syncthreads();
    return *sJob;
}

// ======================================================================
// Big engine: 128x128 tile, 256 threads, 8x8 thread tile, BK=16.
// As[k][m], Ws[k][n] transposed, pad 136 (%4==0 for float4 LDS).
// Staging: row = tid&127, colgroup = (tid>>7)*8 -> conflict-free STS.
// Fragments: rows ty8=(tid>>4)*8 (warp-broadcast), cols tx8=(tid&15)*8.
// ======================================================================
__device__ __forceinline__ void fma8x8(
    float (&acc)[8][8], const float (*As)[136], const float (*Ws)[136],
    int ty8, int tx8)
{
#pragma unroll 8
    for (int k = 0; k < 16; k++) {
        float4 a0 = *(const float4*)&As[k][ty8];
        float4 a1 = *(const float4*)&As[k][ty8 + 4];
        float4 b0 = *(const float4*)&Ws[k][tx8];
        float4 b1 = *(const float4*)&Ws[k][tx8 + 4];
        float a[8] = {a0.x, a0.y, a0.z, a0.w, a1.x, a1.y, a1.z, a1.w};
        float b[8] = {b0.x, b0.y, b0.z, b0.w, b1.x, b1.y, b1.z, b1.w};
#pragma unroll
        for (int i = 0; i < 8; i++)
#pragma unroll
            for (int j = 0; j < 8; j++)
                acc[i][j] += a[i] * b[j];
    }
}

// plain: acc += A[128,K] @ W[128,K]^T ; K = nch*16
__device__ __forceinline__ void mmB(
    const float* __restrict__ A, int lda,
    const float* __restrict__ W, int ldw,
    int nch, float (&acc)[8][8],
    float (*As)[136], float (*Ws)[136])
{
    const int tid = threadIdx.x;
    const int r = tid & 127, cg = (tid >> 7) * 8;
    const int tx8 = (tid & 15) * 8, ty8 = (tid >> 4) * 8;
    const float* pa = A + (size_t)r * lda + cg;
    const float* pw = W + (size_t)r * ldw + cg;
    float4 a0 = *(const float4*)pa,       a1 = *(const float4*)(pa + 4);
    float4 w0 = *(const float4*)pw,       w1 = *(const float4*)(pw + 4);
    for (int c = 0; c < nch; c++) {
        __syncthreads();
        As[cg + 0][r] = a0.x; As[cg + 1][r] = a0.y; As[cg + 2][r] = a0.z; As[cg + 3][r] = a0.w;
        As[cg + 4][r] = a1.x; As[cg + 5][r] = a1.y; As[cg + 6][r] = a1.z; As[cg + 7][r] = a1.w;
        Ws[cg + 0][r] = w0.x; Ws[cg + 1][r] = w0.y; Ws[cg + 2][r] = w0.z; Ws[cg + 3][r] = w0.w;
        Ws[cg + 4][r] = w1.x; Ws[cg + 5][r] = w1.y; Ws[cg + 6][r] = w1.z; Ws[cg + 7][r] = w1.w;
        __syncthreads();
        if (c + 1 < nch) {
            int kn = (c + 1) * 16;
            a0 = *(const float4*)(pa + kn); a1 = *(const float4*)(pa + kn + 4);
            w0 = *(const float4*)(pw + kn); w1 = *(const float4*)(pw + kn + 4);
        }
        fma8x8(acc, As, Ws, ty8, tx8);
    }
}

// head-build: A[r, c] = relu( sum_{q<4} P[q][r,c] + b1[c] (+ tab[x[r]][c]) )
// P pre-offset (m0*Hv + kofs); b1/tab pre-offset (+kofs); xc = x + m0*Sv + t.
template <bool HAS_TAB>
__device__ __forceinline__ void mmB_head(
    const float* __restrict__ P,
    const float* __restrict__ b1,
    const float* __restrict__ tab, const int* __restrict__ xc,
    const float* __restrict__ W, int ldw,
    int nch, float (&acc)[8][8],
    float (*As)[136], float (*Ws)[136])
{
    const int tid = threadIdx.x;
    const int r = tid & 127, cg = (tid >> 7) * 8;
    const int tx8 = (tid & 15) * 8, ty8 = (tid >> 4) * 8;
    const size_t pq = (size_t)Bv * Hv;
    const float* p0 = P + (size_t)r * Hv + cg;
    const float* pb = b1 + cg;
    const float* pt = HAS_TAB ? (tab + (size_t)xc[r * Sv] * Hv + cg) : nullptr;
    const float* pw = W + (size_t)r * ldw + cg;

    float4 a0, a1, w0, w1;
    {
        float4 u0 = *(const float4*)(p0);
        float4 u1 = *(const float4*)(p0 + pq);
        float4 u2 = *(const float4*)(p0 + 2 * pq);
        float4 u3 = *(const float4*)(p0 + 3 * pq);
        float4 bb = *(const float4*)(pb);
        a0.x = u0.x + u1.x + u2.x + u3.x + bb.x;
        a0.y = u0.y + u1.y + u2.y + u3.y + bb.y;
        a0.z = u0.z + u1.z + u2.z + u3.z + bb.z;
        a0.w = u0.w + u1.w + u2.w + u3.w + bb.w;
        float4 v0 = *(const float4*)(p0 + 4);
        float4 v1 = *(const float4*)(p0 + pq + 4);
        float4 v2 = *(const float4*)(p0 + 2 * pq + 4);
        float4 v3 = *(const float4*)(p0 + 3 * pq + 4);
        float4 bc = *(const float4*)(pb + 4);
        a1.x = v0.x + v1.x + v2.x + v3.x + bc.x;
        a1.y = v0.y + v1.y + v2.y + v3.y + bc.y;
        a1.z = v0.z + v1.z + v2.z + v3.z + bc.z;
        a1.w = v0.w + v1.w + v2.w + v3.w + bc.w;
        if (HAS_TAB) {
            float4 t0 = *(const float4*)(pt);
            float4 t1 = *(const float4*)(pt + 4);
            a0.x += t0.x; a0.y += t0.y; a0.z += t0.z; a0.w += t0.w;
            a1.x += t1.x; a1.y += t1.y; a1.z += t1.z; a1.w += t1.w;
        }
        a0.x = fmaxf(a0.x, 0.f); a0.y = fmaxf(a0.y, 0.f); a0.z = fmaxf(a0.z, 0.f); a0.w = fmaxf(a0.w, 0.f);
        a1.x = fmaxf(a1.x, 0.f); a1.y = fmaxf(a1.y, 0.f); a1.z = fmaxf(a1.z, 0.f); a1.w = fmaxf(a1.w, 0.f);
        w0 = *(const float4*)pw; w1 = *(const float4*)(pw + 4);
    }
    for (int c = 0; c < nch; c++) {
        __syncthreads();
        As[cg + 0][r] = a0.x; As[cg + 1][r] = a0.y; As[cg + 2][r] = a0.z; As[cg + 3][r] = a0.w;
        As[cg + 4][r] = a1.x; As[cg + 5][r] = a1.y; As[cg + 6][r] = a1.z; As[cg + 7][r] = a1.w;
        Ws[cg + 0][r] = w0.x; Ws[cg + 1][r] = w0.y; Ws[cg + 2][r] = w0.z; Ws[cg + 3][r] = w0.w;
        Ws[cg + 4][r] = w1.x; Ws[cg + 5][r] = w1.y; Ws[cg + 6][r] = w1.z; Ws[cg + 7][r] = w1.w;
        __syncthreads();
        if (c + 1 < nch) {
            int kn = (c + 1) * 16;
            float4 u0 = *(const float4*)(p0 + kn);
            float4 u1 = *(const float4*)(p0 + pq + kn);
            float4 u2 = *(const float4*)(p0 + 2 * pq + kn);
            float4 u3 = *(const float4*)(p0 + 3 * pq + kn);
            float4 bb = *(const float4*)(pb + kn);
            a0.x = u0.x + u1.x + u2.x + u3.x + bb.x;
            a0.y = u0.y + u1.y + u2.y + u3.y + bb.y;
            a0.z = u0.z + u1.z + u2.z + u3.z + bb.z;
            a0.w = u0.w + u1.w + u2.w + u3.w + bb.w;
            float4 v0 = *(const float4*)(p0 + kn + 4);
            float4 v1 = *(const float4*)(p0 + pq + kn + 4);
            float4 v2 = *(const float4*)(p0 + 2 * pq + kn + 4);
            float4 v3 = *(const float4*)(p0 + 3 * pq + kn + 4);
            float4 bc = *(const float4*)(pb + kn + 4);
            a1.x = v0.x + v1.x + v2.x + v3.x + bc.x;
            a1.y = v0.y + v1.y + v2.y + v3.y + bc.y;
            a1.z = v0.z + v1.z + v2.z + v3.z + bc.z;
            a1.w = v0.w + v1.w + v2.w + v3.w + bc.w;
            if (HAS_TAB) {
                float4 t0 = *(const float4*)(pt + kn);
                float4 t1 = *(const float4*)(pt + kn + 4);
                a0.x += t0.x; a0.y += t0.y; a0.z += t0.z; a0.w += t0.w;
                a1.x += t1.x; a1.y += t1.y; a1.z += t1.z; a1.w += t1.w;
            }
            a0.x = fmaxf(a0.x, 0.f); a0.y = fmaxf(a0.y, 0.f); a0.z = fmaxf(a0.z, 0.f); a0.w = fmaxf(a0.w, 0.f);
            a1.x = fmaxf(a1.x, 0.f); a1.y = fmaxf(a1.y, 0.f); a1.z = fmaxf(a1.z, 0.f); a1.w = fmaxf(a1.w, 0.f);
            w0 = *(const float4*)(pw + kn); w1 = *(const float4*)(pw + kn + 4);
        }
        fma8x8(acc, As, Ws, ty8, tx8);
    }
}

// store 128x128 tile; C pre-offset to (m0, n0)
__device__ __forceinline__ void storeB(float* C, int ldc, float (&acc)[8][8]) {
    const int tx8 = (threadIdx.x & 15) * 8, ty8 = (threadIdx.x >> 4) * 8;
#pragma unroll
    for (int i = 0; i < 8; i++) {
        *(float4*)(C + (size_t)(ty8 + i) * ldc + tx8) =
            make_float4(acc[i][0], acc[i][1], acc[i][2], acc[i][3]);
        *(float4*)(C + (size_t)(ty8 + i) * ldc + tx8 + 4) =
            make_float4(acc[i][4], acc[i][5], acc[i][6], acc[i][7]);
    }
}

// ======================================================================
// Small 64x64 engine (prologue/epilogue only)
// ======================================================================
__device__ __forceinline__ void mm64(
    const float* __restrict__ A, int lda,
    const float* __restrict__ W, int ldw,
    int K, float (&acc)[4][4],
    float (*As)[68], float (*Ws)[68])
{
    const int tid = threadIdx.x;
    const int lr = tid >> 2, lc = (tid & 3) << 2;
    const int tx = tid & 15, ty = tid >> 4;
    const float* pa = A + (size_t)lr * lda + lc;
    const float* pw = W + (size_t)lr * ldw + lc;
    float4 av = *(const float4*)pa;
    float4 wv = *(const float4*)pw;
    for (int k0 = 0; k0 < K; k0 += 16) {
        __syncthreads();
        As[lc + 0][lr] = av.x; As[lc + 1][lr] = av.y;
        As[lc + 2][lr] = av.z; As[lc + 3][lr] = av.w;
        Ws[lc + 0][lr] = wv.x; Ws[lc + 1][lr] = wv.y;
        Ws[lc + 2][lr] = wv.z; Ws[lc + 3][lr] = wv.w;
        __syncthreads();
        if (k0 + 16 < K) {
            av = *(const float4*)(pa + k0 + 16);
            wv = *(const float4*)(pw + k0 + 16);
        }
#pragma unroll
        for (int k = 0; k < 16; k++) {
            float4 a = *(const float4*)&As[k][ty << 2];
            float4 b = *(const float4*)&Ws[k][tx << 2];
            acc[0][0] += a.x * b.x; acc[0][1] += a.x * b.y; acc[0][2] += a.x * b.z; acc[0][3] += a.x * b.w;
            acc[1][0] += a.y * b.x; acc[1][1] += a.y * b.y; acc[1][2] += a.y * b.z; acc[1][3] += a.y * b.w;
            acc[2][0] += a.z * b.x; acc[2][1] += a.z * b.y; acc[2][2] += a.z * b.z; acc[2][3] += a.z * b.w;
            acc[3][0] += a.w * b.x; acc[3][1] += a.w * b.y; acc[3][2] += a.w * b.z; acc[3][3] += a.w * b.w;
        }
    }
}

__device__ __forceinline__ void store_plain(float* C, int ldc, float (&acc)[4][4]) {
    const int tx = threadIdx.x & 15, ty = threadIdx.x >> 4;
#pragma unroll
    for (int i = 0; i < 4; i++)
        *(float4*)(C + (size_t)(ty * 4 + i) * ldc + tx * 4) =
            make_float4(acc[i][0], acc[i][1], acc[i][2], acc[i][3]);
}
__device__ __forceinline__ void store_epi(float* C, int ldc, float (&acc)[4][4],
                                          const float* __restrict__ bias, int relu) {
    const int tx = threadIdx.x & 15, ty = threadIdx.x >> 4;
    float4 bb = *(const float4*)(bias + tx * 4);
#pragma unroll
    for (int i = 0; i < 4; i++) {
        float4 v = make_float4(acc[i][0] + bb.x, acc[i][1] + bb.y,
                               acc[i][2] + bb.z, acc[i][3] + bb.w);
        if (relu) {
            v.x = fmaxf(v.x, 0.f); v.y = fmaxf(v.y, 0.f);
            v.z = fmaxf(v.z, 0.f); v.w = fmaxf(v.w, 0.f);
        }
        *(float4*)(C + (size_t)(ty * 4 + i) * ldc + tx * 4) = v;
    }
}

// ---------------- the one persistent kernel ----------------
__global__ void __launch_bounds__(256, 1) vrnn_persistent(
    const int* __restrict__ x, const float* __restrict__ h0,
    const float* __restrict__ eps,
    const float* __restrict__ phi_x_w, const float* __restrict__ phi_x_b,
    const float* __restrict__ enc_w1, const float* __restrict__ enc_b1,
    const float* __restrict__ enc_w2, const float* __restrict__ enc_b2,
    const float* __restrict__ pri_w1, const float* __restrict__ pri_b1,
    const float* __restrict__ pri_w2, const float* __restrict__ pri_b2,
    const float* __restrict__ phi_z_w, const float* __restrict__ phi_z_b,
    const float* __restrict__ dec_w, const float* __restrict__ dec_b,
    const float* __restrict__ act_w, const float* __restrict__ act_b,
    const float* __restrict__ wih, const float* __restrict__ whh,
    const float* __restrict__ bih, const float* __restrict__ bhh,
    float* __restrict__ out, int out_size)
{
    __shared__ float AsB[16][136], WsB[16][136];
    __shared__ float As[16][68], Ws[16][68];
    __shared__ int sJob;
    __shared__ double sRed[8];

    const int tid = threadIdx.x;
    const int gtid = blockIdx.x * blockDim.x + tid;
    const int nthr = gridDim.x * blockDim.x;
    double kacc = 0.0;

    // ---- P0: PX table ----
    for (int i = gtid; i < Avv * Hv; i += nthr) {
        int a = i >> 10, j = i & 1023;
        g_PX[i] = fmaxf(phi_x_w[(size_t)j * Avv + a] + phi_x_b[j], 0.f);
    }
    grid_sync();

    // ---- P1: ENCX (16) + GIX (48) tiles, mm64, K=1024 ----
    for (;;) {
        int j = next_job(&sJob);
        if (j >= 64) break;
        float acc[4][4] = {};
        if (j < 16) {
            mm64(g_PX, Hv, enc_w1 + (size_t)j * 64 * 2048, 2048, Hv, acc, As, Ws);
            store_plain(g_ENCX + j * 64, Hv, acc);
        } else {
            int nb = j - 16;
            mm64(g_PX, Hv, wih + (size_t)nb * 64 * 2048, 2048, Hv, acc, As, Ws);
            store_plain(g_GIX + nb * 64, H3, acc);
        }
    }
    grid_sync();

    // ================= recurrent steps =================
    for (int t = 0; t < Sv; t++) {
        const float* hcur = (t == 0) ? h0 : g_hbuf[(t + 1) & 1];
        float* hnext = g_hbuf[t & 1];

        // ---- Ph1: enc (64) + pri (64) + gh[0..24) = 152 jobs, all K=256 ----
        for (;;) {
            int j = next_job(&sJob);
            if (j >= 152) break;
            float acc[8][8] = {};
            if (j < 64) {
                int ks = j & 3, nb = (j >> 2) & 7, mb = j >> 5;
                mmB(hcur + (size_t)mb * 128 * Hv + ks * 256, Hv,
                    enc_w1 + (size_t)nb * 128 * 2048 + 1024 + ks * 256, 2048,
                    16, acc, AsB, WsB);
                storeB(g_h1encp[ks] + (size_t)mb * 128 * Hv + nb * 128, Hv, acc);
            } else if (j < 128) {
                int q = j - 64;
                int ks = q & 3, nb = (q >> 2) & 7, mb = q >> 5;
                mmB(hcur + (size_t)mb * 128 * Hv + ks * 256, Hv,
                    pri_w1 + (size_t)nb * 128 * Hv + ks * 256, Hv,
                    16, acc, AsB, WsB);
                storeB(g_h1prip[ks] + (size_t)mb * 128 * Hv + nb * 128, Hv, acc);
            } else {
                int i = j - 128;                    // gh 0..23
                int ks = i & 3, c = i >> 2, nb = c % 24, mb = c / 24;
                mmB(hcur + (size_t)mb * 128 * Hv + ks * 256, Hv,
                    whh + (size_t)nb * 128 * Hv + ks * 256, Hv,
                    16, acc, AsB, WsB);
                storeB(g_ghp[ks] + (size_t)mb * 128 * H3 + nb * 128, H3, acc);
            }
        }
        grid_sync();

        // ---- Ph2: gh[24..144) (120 big, first) + heads (64 half) ----
        for (;;) {
            int j = next_job(&sJob);
            if (j >= 184) break;
            float acc[8][8] = {};
            if (j < 120) {
                int i = 24 + j;
                int ks = i & 3, c = i >> 2, nb = c % 24, mb = c / 24;
                mmB(hcur + (size_t)mb * 128 * Hv + ks * 256, Hv,
                    whh + (size_t)nb * 128 * Hv + ks * 256, Hv,
                    16, acc, AsB, WsB);
                storeB(g_ghp[ks] + (size_t)mb * 128 * H3 + nb * 128, H3, acc);
            } else {
                int q = j - 120;                    // 0..63
                int ks = q & 7, zb = (q >> 3) & 1, mb = (q >> 4) & 1, typ = (q >> 5) & 1;
                int m0 = mb * 128, n0 = zb * 128, kofs = ks * 128;
                if (typ == 0) {
                    mmB_head<true>(g_h1encp[0] + (size_t)m0 * Hv + kofs,
                                   enc_b1 + kofs, g_ENCX + kofs, x + (size_t)m0 * Sv + t,
                                   enc_w2 + (size_t)n0 * Hv + kofs, Hv,
                                   8, acc, AsB, WsB);
                    storeB(g_hdencp[ks] + (size_t)m0 * Zv + n0, Zv, acc);
                } else {
                    mmB_head<false>(g_h1prip[0] + (size_t)m0 * Hv + kofs,
                                    pri_b1 + kofs, nullptr, nullptr,
                                    pri_w2 + (size_t)n0 * Hv + kofs, Hv,
                                    8, acc, AsB, WsB);
                    storeB(g_hdprip[ks] + (size_t)m0 * Zv + n0, Zv, acc);
                }
            }
        }
        grid_sync();

        // ---- Ph3: softplus + KLD + z ----
        {
            const float* ep = eps + (size_t)t * Bv * Zv;
            for (int i = gtid; i < Bv * Zv; i += nthr) {
                int zc = i & 255;
                float e = enc_b2[zc], p = pri_b2[zc];
#pragma unroll
                for (int q = 0; q < KS2; q++) { e += g_hdencp[q][i]; p += g_hdprip[q][i]; }
                float es = softplusf(e), ps = softplusf(p);
                float d = e - p;
                kacc += (double)(2.f * (logf(ps) - logf(es))
                                 + (es * es + d * d) / (ps * ps) - 1.f);
                g_zbuf[i] = ep[i] * es + e;
            }
        }
        grid_sync();

        // ---- Ph4: pz partials (64 jobs, K=64) ----
        for (;;) {
            int j = next_job(&sJob);
            if (j >= 64) break;
            float acc[8][8] = {};
            int ks = j & 3, nb = (j >> 2) & 7, mb = (j >> 5) & 1;
            mmB(g_zbuf + (size_t)mb * 128 * Zv + ks * 64, Zv,
                phi_z_w + (size_t)nb * 128 * Zv + ks * 64, Zv,
                4, acc, AsB, WsB);
            storeB(g_pzp[ks] + (size_t)mb * 128 * Hv + nb * 128, Hv, acc);
        }
        grid_sync();

        // ---- Ph5: gh[144..192) (48 big) + gi (192 big) = 240 jobs ----
        for (;;) {
            int j = next_job(&sJob);
            if (j >= 240) break;
            float acc[8][8] = {};
            if (j < 48) {
                int i = 144 + j;
                int ks = i & 3, c = i >> 2, nb = c % 24, mb = c / 24;
                mmB(hcur + (size_t)mb * 128 * Hv + ks * 256, Hv,
                    whh + (size_t)nb * 128 * Hv + ks * 256, Hv,
                    16, acc, AsB, WsB);
                storeB(g_ghp[ks] + (size_t)mb * 128 * H3 + nb * 128, H3, acc);
            } else {
                int q = j - 48;                     // 0..191
                int ks = q & 3, c = q >> 2, nb = c % 24, mb = c / 24;
                int m0 = mb * 128, kofs = ks * 256;
                mmB_head<false>(g_pzp[0] + (size_t)m0 * Hv + kofs,
                                phi_z_b + kofs, nullptr, nullptr,
                                wih + (size_t)nb * 128 * 2048 + 1024 + kofs, 2048,
                                16, acc, AsB, WsB);
                storeB(g_gip[ks] + (size_t)m0 * H3 + nb * 128, H3, acc);
            }
        }
        grid_sync();

        // ---- Ph6: GRU gates ----
        for (int i = gtid; i < Bv * Hv; i += nthr) {
            int m = i >> 10, j = i & 1023;
            int xm = x[(size_t)m * Sv + t];
            size_t b3 = (size_t)m * H3;
            size_t tb = (size_t)xm * H3;
            float gr = bih[j] + g_GIX[tb + j];
            float gz = bih[Hv + j] + g_GIX[tb + Hv + j];
            float gn = bih[2 * Hv + j] + g_GIX[tb + 2 * Hv + j];
            float hr = bhh[j], hz = bhh[Hv + j], hn = bhh[2 * Hv + j];
#pragma unroll
            for (int q = 0; q < KS1; q++) {
                gr += g_gip[q][b3 + j];          hr += g_ghp[q][b3 + j];
                gz += g_gip[q][b3 + Hv + j];     hz += g_ghp[q][b3 + Hv + j];
                gn += g_gip[q][b3 + 2 * Hv + j]; hn += g_ghp[q][b3 + 2 * Hv + j];
            }
            float r = sigmoidf(gr + hr);
            float zg = sigmoidf(gz + hz);
            float n = tanhf(gn + r * hn);
            hnext[i] = (1.f - zg) * n + zg * hcur[i];
        }
        grid_sync();
    }

    // ================= epilogue (mm64 path, one-time) =================
    const float* hF = g_hbuf[1];

    for (;;) {
        int j = next_job(&sJob);
        if (j >= 64) break;
        float acc[4][4] = {};
        int mb = j >> 4, nb = j & 15;
        mm64(hF + (size_t)mb * 64 * Hv, Hv,
             pri_w1 + (size_t)nb * 64 * Hv, Hv, Hv, acc, As, Ws);
        store_epi(g_fh1 + (size_t)mb * 64 * Hv + nb * 64, Hv, acc, pri_b1 + nb * 64, 1);
    }
    grid_sync();

    for (;;) {
        int j = next_job(&sJob);
        if (j >= 16) break;
        float acc[4][4] = {};
        int mb = j >> 2, nb = j & 3;
        mm64(g_fh1 + (size_t)mb * 64 * Hv, Hv,
             pri_w2 + (size_t)nb * 64 * Hv, Hv, Hv, acc, As, Ws);
        store_epi(g_fpri + (size_t)mb * 64 * Zv + nb * 64, Zv, acc, pri_b2 + nb * 64, 0);
    }
    grid_sync();

    {
        const float* ep = eps + (size_t)Sv * Bv * Zv;
        for (int i = gtid; i < Bv * Zv; i += nthr) {
            float p = g_fpri[i];
            g_zbuf[i] = ep[i] * softplusf(p) + p;
        }
    }
    grid_sync();

    for (;;) {
        int j = next_job(&sJob);
        if (j >= 64) break;
        float acc[4][4] = {};
        int mb = j >> 4, nb = j & 15;
        mm64(g_zbuf + (size_t)mb * 64 * Zv, Zv,
             phi_z_w + (size_t)nb * 64 * Zv, Zv, Zv, acc, As, Ws);
        store_epi(g_pz + (size_t)mb * 64 * Hv + nb * 64, Hv, acc, phi_z_b + nb * 64, 1);
    }
    grid_sync();

    for (;;) {
        int j = next_job(&sJob);
        if (j >= 64) break;
        float acc[4][4] = {};
        int mb = j >> 4, nb = j & 15;
        mm64(g_pz + (size_t)mb * 64 * Hv, Hv,
             dec_w + (size_t)nb * 64 * 2048, 2048, Hv, acc, As, Ws);
        mm64(hF + (size_t)mb * 64 * Hv, Hv,
             dec_w + (size_t)nb * 64 * 2048 + 1024, 2048, Hv, acc, As, Ws);
        store_epi(g_decb + (size_t)mb * 64 * Hv + nb * 64, Hv, acc, dec_b + nb * 64, 1);
    }
    grid_sync();

    for (;;) {
        int j = next_job(&sJob);
        if (j >= 4) break;
        float acc[4][4] = {};
        mm64(g_decb + (size_t)j * 64 * Hv, Hv, act_w, Hv, Hv, acc, As, Ws);
        store_epi(out + (size_t)j * 64 * Avv, Avv, acc, act_b, 0);
    }
    {
        double v = kacc;
#pragma unroll
        for (int off = 16; off > 0; off >>= 1)
            v += __shfl_down_sync(0xffffffffu, v, off);
        if ((tid & 31) == 0) sRed[tid >> 5] = v;
        __syncthreads();
        if (tid == 0) {
            double s = 0.0;
            for (int w = 0; w < 8; w++) s += sRed[w];
            g_kldp[blockIdx.x] = s;
        }
    }
    grid_sync();

    if (blockIdx.x == 0 && tid == 0) {
        double s = 0.0;
        for (unsigned b = 0; b < gridDim.x; b++) s += g_kldp[b];
        out[out_size - 1] = (float)(0.5 * s);
    }
}

// ---------------- host launch: ONE kernel node ----------------
extern "C" void kernel_launch(void* const* d_in, const int* in_sizes, int n_in,
                              void* d_out, int out_size)
{
    int dev = 0;
    cudaGetDevice(&dev);
    int sms = 0;
    cudaDeviceGetAttribute(&sms, cudaDevAttrMultiProcessorCount, dev);
    if (sms < 1) sms = 148;
    if (sms > 1024) sms = 1024;

    vrnn_persistent<<<sms, 256>>>(
        (const int*)d_in[0], (const float*)d_in[1], (const float*)d_in[2],
        (const float*)d_in[3], (const float*)d_in[4],
        (const float*)d_in[5], (const float*)d_in[6],
        (const float*)d_in[7], (const float*)d_in[8],
        (const float*)d_in[9], (const float*)d_in[10],
        (const float*)d_in[11], (const float*)d_in[12],
        (const float*)d_in[13], (const float*)d_in[14],
        (const float*)d_in[15], (const float*)d_in[16],
        (const float*)d_in[17], (const float*)d_in[18],
        (const float*)d_in[19], (const float*)d_in[20],
        (const float*)d_in[21], (const float*)d_in[22],
        (float*)d_out, out_size);
}

// round 16
// speedup vs baseline: 1.3135x; 1.2504x over previous
#include <cuda_runtime.h>
#include <math.h>

#define Bv 256
#define Sv 512
#define Avv 64
#define Hv 1024
#define Zv 256
#define H3 3072
#define KS1 4
#define KS2 8

// ---------------- device scratch (static: no allocations) ----------------
__device__ float g_hbuf[2][Bv * Hv];
__device__ float g_PX[Avv * Hv];
__device__ float g_ENCX[Avv * Hv];
__device__ float g_GIX[Avv * H3];
__device__ float g_h1encp[KS1][Bv * Hv];
__device__ float g_h1prip[KS1][Bv * Hv];
__device__ float g_ghp[KS1][Bv * H3];
__device__ float g_gip[KS1][Bv * H3];
__device__ float g_hdencp[KS2][Bv * Zv];
__device__ float g_hdprip[KS2][Bv * Zv];
__device__ float g_zbuf[Bv * Zv];
__device__ float g_pz[Bv * Hv];
__device__ float g_fh1[Bv * Hv];
__device__ float g_fpri[Bv * Zv];
__device__ float g_decb[Bv * Hv];
__device__ double g_kldp[1024];
__device__ unsigned g_arrive, g_release, g_work;

// ---------------- helpers ----------------
__device__ __forceinline__ float softplusf(float x) {
    return x > 0.f ? x + log1pf(expf(-x)) : log1pf(expf(x));
}
__device__ __forceinline__ float sigmoidf(float x) {
    return 1.f / (1.f + expf(-x));
}

// grid-wide barrier; also resets the work counter for the next phase.
__device__ __forceinline__ void grid_sync() {
    __syncthreads();
    if (threadIdx.x == 0) {
        __threadfence();
        volatile unsigned* rel = &g_release;
        unsigned gen = *rel;
        if (atomicAdd(&g_arrive, 1u) == gridDim.x - 1u) {
            g_arrive = 0u;
            g_work = 0u;
            __threadfence();
            atomicAdd(&g_release, 1u);
        } else {
            while (*rel == gen) __nanosleep(32);
        }
    }
    __syncthreads();
    __threadfence();
}

__device__ __forceinline__ int next_job(int* sJob) {
    __syncthreads();
    if (threadIdx.x == 0) *sJob = (int)atomicAdd(&g_work, 1u);
    __syncthreads();
    return *sJob;
}

// ---------------- 64x64 fp32 tile: acc += A[64,K] @ W[64,K]^T ----------------
// 256 threads, thread-tile 4x4, BK=16, register double-buffered global loads.
__device__ __forceinline__ void mm64(
    const float* __restrict__ A, int lda,
    const float* __restrict__ W, int ldw,
    int K, float (&acc)[4][4],
    float (*As)[68], float (*Ws)[68])
{
    const int tid = threadIdx.x;
    const int lr = tid >> 2, lc = (tid & 3) << 2;
    const int tx = tid & 15, ty = tid >> 4;
    const float* pa = A + (size_t)lr * lda + lc;
    const float* pw = W + (size_t)lr * ldw + lc;
    float4 av = *(const float4*)pa;
    float4 wv = *(const float4*)pw;
    for (int k0 = 0; k0 < K; k0 += 16) {
        __syncthreads();
        As[lc + 0][lr] = av.x; As[lc + 1][lr] = av.y;
        As[lc + 2][lr] = av.z; As[lc + 3][lr] = av.w;
        Ws[lc + 0][lr] = wv.x; Ws[lc + 1][lr] = wv.y;
        Ws[lc + 2][lr] = wv.z; Ws[lc + 3][lr] = wv.w;
        __syncthreads();
        if (k0 + 16 < K) {
            av = *(const float4*)(pa + k0 + 16);
            wv = *(const float4*)(pw + k0 + 16);
        }
#pragma unroll
        for (int k = 0; k < 16; k++) {
            float4 a = *(const float4*)&As[k][ty << 2];
            float4 b = *(const float4*)&Ws[k][tx << 2];
            acc[0][0] += a.x * b.x; acc[0][1] += a.x * b.y; acc[0][2] += a.x * b.z; acc[0][3] += a.x * b.w;
            acc[1][0] += a.y * b.x; acc[1][1] += a.y * b.y; acc[1][2] += a.y * b.z; acc[1][3] += a.y * b.w;
            acc[2][0] += a.z * b.x; acc[2][1] += a.z * b.y; acc[2][2] += a.z * b.z; acc[2][3] += a.z * b.w;
            acc[3][0] += a.w * b.x; acc[3][1] += a.w * b.y; acc[3][2] += a.w * b.z; acc[3][3] += a.w * b.w;
        }
    }
}

// Head-GEMM tile: A built on the fly = relu(sum of KS1 partials + bias [+ tab[x]]).
__device__ __forceinline__ void mm64_head(
    const float* __restrict__ P, int pstride,
    const float* __restrict__ b1,
    const float* __restrict__ tab, const int* __restrict__ xc,
    const float* __restrict__ W, int ldw,
    int K, float (&acc)[4][4],
    float (*As)[68], float (*Ws)[68])
{
    const int tid = threadIdx.x;
    const int lr = tid >> 2, lc = (tid & 3) << 2;
    const int tx = tid & 15, ty = tid >> 4;
    const float* p0 = P + (size_t)lr * Hv + lc;
    const float* pw = W + (size_t)lr * ldw + lc;
    const float* pt = nullptr;
    if (tab) pt = tab + (size_t)xc[lr * Sv] * Hv + lc;
    for (int k0 = 0; k0 < K; k0 += 16) {
        float4 a0 = *(const float4*)(p0 + k0);
        float4 a1 = *(const float4*)(p0 + pstride + k0);
        float4 a2 = *(const float4*)(p0 + 2 * pstride + k0);
        float4 a3 = *(const float4*)(p0 + 3 * pstride + k0);
        float4 bb = *(const float4*)(b1 + k0 + lc);
        float4 wv = *(const float4*)(pw + k0);
        float4 av;
        av.x = a0.x + a1.x + a2.x + a3.x + bb.x;
        av.y = a0.y + a1.y + a2.y + a3.y + bb.y;
        av.z = a0.z + a1.z + a2.z + a3.z + bb.z;
        av.w = a0.w + a1.w + a2.w + a3.w + bb.w;
        if (pt) {
            float4 tv = *(const float4*)(pt + k0);
            av.x += tv.x; av.y += tv.y; av.z += tv.z; av.w += tv.w;
        }
        av.x = fmaxf(av.x, 0.f); av.y = fmaxf(av.y, 0.f);
        av.z = fmaxf(av.z, 0.f); av.w = fmaxf(av.w, 0.f);
        __syncthreads();
        As[lc + 0][lr] = av.x; As[lc + 1][lr] = av.y;
        As[lc + 2][lr] = av.z; As[lc + 3][lr] = av.w;
        Ws[lc + 0][lr] = wv.x; Ws[lc + 1][lr] = wv.y;
        Ws[lc + 2][lr] = wv.z; Ws[lc + 3][lr] = wv.w;
        __syncthreads();
#pragma unroll
        for (int k = 0; k < 16; k++) {
            float4 a = *(const float4*)&As[k][ty << 2];
            float4 b = *(const float4*)&Ws[k][tx << 2];
            acc[0][0] += a.x * b.x; acc[0][1] += a.x * b.y; acc[0][2] += a.x * b.z; acc[0][3] += a.x * b.w;
            acc[1][0] += a.y * b.x; acc[1][1] += a.y * b.y; acc[1][2] += a.y * b.z; acc[1][3] += a.y * b.w;
            acc[2][0] += a.z * b.x; acc[2][1] += a.z * b.y; acc[2][2] += a.z * b.z; acc[2][3] += a.z * b.w;
            acc[3][0] += a.w * b.x; acc[3][1] += a.w * b.y; acc[3][2] += a.w * b.z; acc[3][3] += a.w * b.w;
        }
    }
}

__device__ __forceinline__ void store_plain(float* C, int ldc, float (&acc)[4][4]) {
    const int tx = threadIdx.x & 15, ty = threadIdx.x >> 4;
#pragma unroll
    for (int i = 0; i < 4; i++)
        *(float4*)(C + (size_t)(ty * 4 + i) * ldc + tx * 4) =
            make_float4(acc[i][0], acc[i][1], acc[i][2], acc[i][3]);
}
__device__ __forceinline__ void store_epi(float* C, int ldc, float (&acc)[4][4],
                                          const float* __restrict__ bias, int relu) {
    const int tx = threadIdx.x & 15, ty = threadIdx.x >> 4;
    float4 bb = *(const float4*)(bias + tx * 4);
#pragma unroll
    for (int i = 0; i < 4; i++) {
        float4 v = make_float4(acc[i][0] + bb.x, acc[i][1] + bb.y,
                               acc[i][2] + bb.z, acc[i][3] + bb.w);
        if (relu) {
            v.x = fmaxf(v.x, 0.f); v.y = fmaxf(v.y, 0.f);
            v.z = fmaxf(v.z, 0.f); v.w = fmaxf(v.w, 0.f);
        }
        *(float4*)(C + (size_t)(ty * 4 + i) * ldc + tx * 4) = v;
    }
}

// ---------------- the one persistent kernel (2 blocks / SM) ----------------
__global__ void __launch_bounds__(256, 2) vrnn_persistent(
    const int* __restrict__ x, const float* __restrict__ h0,
    const float* __restrict__ eps,
    const float* __restrict__ phi_x_w, const float* __restrict__ phi_x_b,
    const float* __restrict__ enc_w1, const float* __restrict__ enc_b1,
    const float* __restrict__ enc_w2, const float* __restrict__ enc_b2,
    const float* __restrict__ pri_w1, const float* __restrict__ pri_b1,
    const float* __restrict__ pri_w2, const float* __restrict__ pri_b2,
    const float* __restrict__ phi_z_w, const float* __restrict__ phi_z_b,
    const float* __restrict__ dec_w, const float* __restrict__ dec_b,
    const float* __restrict__ act_w, const float* __restrict__ act_b,
    const float* __restrict__ wih, const float* __restrict__ whh,
    const float* __restrict__ bih, const float* __restrict__ bhh,
    float* __restrict__ out, int out_size)
{
    __shared__ float As[16][68], Ws[16][68];
    __shared__ int sJob;
    __shared__ double sRed[8];

    const int tid = threadIdx.x;
    const int gtid = blockIdx.x * blockDim.x + tid;
    const int nthr = gridDim.x * blockDim.x;
    double kacc = 0.0;

    // ---- P0: PX table ----
    for (int i = gtid; i < Avv * Hv; i += nthr) {
        int a = i >> 10, j = i & 1023;
        g_PX[i] = fmaxf(phi_x_w[(size_t)j * Avv + a] + phi_x_b[j], 0.f);
    }
    grid_sync();

    // ---- P1: ENCX (16) + GIX (48) tiles, K=1024 ----
    for (;;) {
        int j = next_job(&sJob);
        if (j >= 64) break;
        float acc[4][4] = {};
        if (j < 16) {
            mm64(g_PX, Hv, enc_w1 + (size_t)j * 64 * 2048, 2048, Hv, acc, As, Ws);
            store_plain(g_ENCX + j * 64, Hv, acc);
        } else {
            int nb = j - 16;
            mm64(g_PX, Hv, wih + (size_t)nb * 64 * 2048, 2048, Hv, acc, As, Ws);
            store_plain(g_GIX + nb * 64, H3, acc);
        }
    }
    grid_sync();

    // ================= recurrent steps =================
    for (int t = 0; t < Sv; t++) {
        const float* hcur = (t == 0) ? h0 : g_hbuf[(t + 1) & 1];
        float* hnext = g_hbuf[t & 1];

        // ---- S1: h1enc partials (256) | h1pri partials (256) | gh partials (768) ----
        for (;;) {
            int j = next_job(&sJob);
            if (j >= 1280) break;
            float acc[4][4] = {};
            if (j < 256) {
                int ks = j & 3, r = j >> 2, mb = r >> 4, nb = r & 15;
                mm64(hcur + (size_t)mb * 64 * Hv + ks * 256, Hv,
                     enc_w1 + (size_t)nb * 64 * 2048 + 1024 + ks * 256, 2048,
                     256, acc, As, Ws);
                store_plain(g_h1encp[ks] + (size_t)mb * 64 * Hv + nb * 64, Hv, acc);
            } else if (j < 512) {
                int q = j - 256;
                int ks = q & 3, r = q >> 2, mb = r >> 4, nb = r & 15;
                mm64(hcur + (size_t)mb * 64 * Hv + ks * 256, Hv,
                     pri_w1 + (size_t)nb * 64 * Hv + ks * 256, Hv,
                     256, acc, As, Ws);
                store_plain(g_h1prip[ks] + (size_t)mb * 64 * Hv + nb * 64, Hv, acc);
            } else {
                int q = j - 512;
                int ks = q & 3, r = q >> 2, mb = r / 48, nb = r % 48;
                mm64(hcur + (size_t)mb * 64 * Hv + ks * 256, Hv,
                     whh + (size_t)nb * 64 * Hv + ks * 256, Hv,
                     256, acc, As, Ws);
                store_plain(g_ghp[ks] + (size_t)mb * 64 * H3 + nb * 64, H3, acc);
            }
        }
        grid_sync();

        // ---- S2: head GEMM partials, K split 8 (enc 128 | pri 128 jobs) ----
        for (;;) {
            int j = next_job(&sJob);
            if (j >= 256) break;
            float acc[4][4] = {};
            int jj = j & 127, typ = j >> 7;
            int ks = jj & 7, r = jj >> 3, mb = r >> 2, zb = r & 3;
            int kofs = ks * 128, m0 = mb * 64;
            if (typ == 0) {
                mm64_head(g_h1encp[0] + (size_t)m0 * Hv + kofs, Bv * Hv,
                          enc_b1 + kofs, g_ENCX + kofs, x + (size_t)m0 * Sv + t,
                          enc_w2 + (size_t)zb * 64 * Hv + kofs, Hv,
                          128, acc, As, Ws);
                store_plain(g_hdencp[ks] + (size_t)m0 * Zv + zb * 64, Zv, acc);
            } else {
                mm64_head(g_h1prip[0] + (size_t)m0 * Hv + kofs, Bv * Hv,
                          pri_b1 + kofs, nullptr, nullptr,
                          pri_w2 + (size_t)zb * 64 * Hv + kofs, Hv,
                          128, acc, As, Ws);
                store_plain(g_hdprip[ks] + (size_t)m0 * Zv + zb * 64, Zv, acc);
            }
        }
        grid_sync();

        // ---- S3: softplus + KLD + z ----
        {
            const float* ep = eps + (size_t)t * Bv * Zv;
            for (int i = gtid; i < Bv * Zv; i += nthr) {
                int zc = i & 255;
                float e = enc_b2[zc], p = pri_b2[zc];
#pragma unroll
                for (int q = 0; q < KS2; q++) { e += g_hdencp[q][i]; p += g_hdprip[q][i]; }
                float es = softplusf(e), ps = softplusf(p);
                float d = e - p;
                kacc += (double)(2.f * (logf(ps) - logf(es))
                                 + (es * es + d * d) / (ps * ps) - 1.f);
                g_zbuf[i] = ep[i] * es + e;
            }
        }
        grid_sync();

        // ---- S4: pz = relu(z @ phi_z_w^T + b) (64 tiles, K=256) ----
        for (;;) {
            int j = next_job(&sJob);
            if (j >= 64) break;
            float acc[4][4] = {};
            int mb = j >> 4, nb = j & 15;
            mm64(g_zbuf + (size_t)mb * 64 * Zv, Zv,
                 phi_z_w + (size_t)nb * 64 * Zv, Zv, Zv, acc, As, Ws);
            store_epi(g_pz + (size_t)mb * 64 * Hv + nb * 64, Hv, acc,
                      phi_z_b + nb * 64, 1);
        }
        grid_sync();

        // ---- S5: gi partials = pz @ wihR^T, K split 4 (768 jobs) ----
        for (;;) {
            int j = next_job(&sJob);
            if (j >= 768) break;
            float acc[4][4] = {};
            int ks = j & 3, r = j >> 2, mb = r / 48, nb = r % 48;
            mm64(g_pz + (size_t)mb * 64 * Hv + ks * 256, Hv,
                 wih + (size_t)nb * 64 * 2048 + 1024 + ks * 256, 2048,
                 256, acc, As, Ws);
            store_plain(g_gip[ks] + (size_t)mb * 64 * H3 + nb * 64, H3, acc);
        }
        grid_sync();

        // ---- S6: GRU gates ----
        for (int i = gtid; i < Bv * Hv; i += nthr) {
            int m = i >> 10, j = i & 1023;
            int xm = x[(size_t)m * Sv + t];
            size_t b3 = (size_t)m * H3;
            size_t tb = (size_t)xm * H3;
            float gr = bih[j] + g_GIX[tb + j];
            float gz = bih[Hv + j] + g_GIX[tb + Hv + j];
            float gn = bih[2 * Hv + j] + g_GIX[tb + 2 * Hv + j];
            float hr = bhh[j], hz = bhh[Hv + j], hn = bhh[2 * Hv + j];
#pragma unroll
            for (int q = 0; q < KS1; q++) {
                gr += g_gip[q][b3 + j];          hr += g_ghp[q][b3 + j];
                gz += g_gip[q][b3 + Hv + j];     hz += g_ghp[q][b3 + Hv + j];
                gn += g_gip[q][b3 + 2 * Hv + j]; hn += g_ghp[q][b3 + 2 * Hv + j];
            }
            float r = sigmoidf(gr + hr);
            float zg = sigmoidf(gz + hz);
            float n = tanhf(gn + r * hn);
            hnext[i] = (1.f - zg) * n + zg * hcur[i];
        }
        grid_sync();
    }

    // ================= epilogue =================
    const float* hF = g_hbuf[1];

    for (;;) {
        int j = next_job(&sJob);
        if (j >= 64) break;
        float acc[4][4] = {};
        int mb = j >> 4, nb = j & 15;
        mm64(hF + (size_t)mb * 64 * Hv, Hv,
             pri_w1 + (size_t)nb * 64 * Hv, Hv, Hv, acc, As, Ws);
        store_epi(g_fh1 + (size_t)mb * 64 * Hv + nb * 64, Hv, acc, pri_b1 + nb * 64, 1);
    }
    grid_sync();

    for (;;) {
        int j = next_job(&sJob);
        if (j >= 16) break;
        float acc[4][4] = {};
        int mb = j >> 2, nb = j & 3;
        mm64(g_fh1 + (size_t)mb * 64 * Hv, Hv,
             pri_w2 + (size_t)nb * 64 * Hv, Hv, Hv, acc, As, Ws);
        store_epi(g_fpri + (size_t)mb * 64 * Zv + nb * 64, Zv, acc, pri_b2 + nb * 64, 0);
    }
    grid_sync();

    {
        const float* ep = eps + (size_t)Sv * Bv * Zv;
        for (int i = gtid; i < Bv * Zv; i += nthr) {
            float p = g_fpri[i];
            g_zbuf[i] = ep[i] * softplusf(p) + p;
        }
    }
    grid_sync();

    for (;;) {
        int j = next_job(&sJob);
        if (j >= 64) break;
        float acc[4][4] = {};
        int mb = j >> 4, nb = j & 15;
        mm64(g_zbuf + (size_t)mb * 64 * Zv, Zv,
             phi_z_w + (size_t)nb * 64 * Zv, Zv, Zv, acc, As, Ws);
        store_epi(g_pz + (size_t)mb * 64 * Hv + nb * 64, Hv, acc, phi_z_b + nb * 64, 1);
    }
    grid_sync();

    for (;;) {
        int j = next_job(&sJob);
        if (j >= 64) break;
        float acc[4][4] = {};
        int mb = j >> 4, nb = j & 15;
        mm64(g_pz + (size_t)mb * 64 * Hv, Hv,
             dec_w + (size_t)nb * 64 * 2048, 2048, Hv, acc, As, Ws);
        mm64(hF + (size_t)mb * 64 * Hv, Hv,
             dec_w + (size_t)nb * 64 * 2048 + 1024, 2048, Hv, acc, As, Ws);
        store_epi(g_decb + (size_t)mb * 64 * Hv + nb * 64, Hv, acc, dec_b + nb * 64, 1);
    }
    grid_sync();

    for (;;) {
        int j = next_job(&sJob);
        if (j >= 4) break;
        float acc[4][4] = {};
        mm64(g_decb + (size_t)j * 64 * Hv, Hv, act_w, Hv, Hv, acc, As, Ws);
        store_epi(out + (size_t)j * 64 * Avv, Avv, acc, act_b, 0);
    }
    {
        double v = kacc;
#pragma unroll
        for (int off = 16; off > 0; off >>= 1)
            v += __shfl_down_sync(0xffffffffu, v, off);
        if ((tid & 31) == 0) sRed[tid >> 5] = v;
        __syncthreads();
        if (tid == 0) {
            double s = 0.0;
            for (int w = 0; w < 8; w++) s += sRed[w];
            g_kldp[blockIdx.x] = s;
        }
    }
    grid_sync();

    if (blockIdx.x == 0 && tid == 0) {
        double s = 0.0;
        for (unsigned b = 0; b < gridDim.x; b++) s += g_kldp[b];
        out[out_size - 1] = (float)(0.5 * s);
    }
}

// ---------------- host launch: ONE kernel node, 2 blocks per SM ----------------
extern "C" void kernel_launch(void* const* d_in, const int* in_sizes, int n_in,
                              void* d_out, int out_size)
{
    int dev = 0;
    cudaGetDevice(&dev);
    int sms = 0;
    cudaDeviceGetAttribute(&sms, cudaDevAttrMultiProcessorCount, dev);
    if (sms < 1) sms = 148;
    int blocks = 2 * sms;
    if (blocks > 1024) blocks = 1024;

    vrnn_persistent<<<blocks, 256>>>(
        (const int*)d_in[0], (const float*)d_in[1], (const float*)d_in[2],
        (const float*)d_in[3], (const float*)d_in[4],
        (const float*)d_in[5], (const float*)d_in[6],
        (const float*)d_in[7], (const float*)d_in[8],
        (const float*)d_in[9], (const float*)d_in[10],
        (const float*)d_in[11], (const float*)d_in[12],
        (const float*)d_in[13], (const float*)d_in[14],
        (const float*)d_in[15], (const float*)d_in[16],
        (const float*)d_in[17], (const float*)d_in[18],
        (const float*)d_in[19], (const float*)d_in[20],
        (const float*)d_in[21], (const float*)d_in[22],
        (float*)d_out, out_size);
}